// round 1
// baseline (speedup 1.0000x reference)
#include <cuda_runtime.h>
#include <cstdint>

// Problem constants
// x: (8, 1024, 3, 1024) fp32; streams s=0(H),1(T),2(R)
// M = 8*1024 = 8192 rows per stream; D=1024; H=16 heads x 64
//
// Pipeline:
//  1) sgemm128 x9 : q/k/v projections -> g_qkv[p][s][m*1024 + (h*64+d)]
//  2) scores128   : g_S[s][bh][i*1024+j] = q_s . k_s  (raw dot, scale applied later)
//  3) attn_pv     : out-stream o uses (S_a + S_b)*0.0625, online softmax, @V -> g_O
//  4) sgemm128 x3 : output projection + bo -> d_out (B,L,3,D) layout

__device__ float g_qkv[3][3][8388608];   // [p: q/k/v][s][8192*1024]  ~302 MB
__device__ float g_S[3][128][1048576];   // [s][bh][1024*1024]        ~1.6 GB
__device__ float g_O[3][8388608];        // [s][8192*1024]            ~100 MB

// ---------- packed f32x2 helpers ----------
__device__ __forceinline__ unsigned long long pk2(float lo, float hi) {
    unsigned long long r;
    asm("mov.b64 %0, {%1, %2};" : "=l"(r) : "f"(lo), "f"(hi));
    return r;
}
__device__ __forceinline__ void ffma2(unsigned long long& d, unsigned long long a, unsigned long long b) {
    asm("fma.rn.f32x2 %0, %1, %2, %0;" : "+l"(d) : "l"(a), "l"(b));
}

// ============================================================
// Kernel 1/4: SGEMM  C[m][n] = sum_k A[m*lda+k]*W[k*1024+n] + bias[n]
// M=8192 (grid.y=64), N=1024 (grid.x=8), K=1024. 128x128 tile, BK=8,
// 256 threads, 8x8 per thread, f32x2 accumulators.
// ============================================================
__global__ __launch_bounds__(256) void sgemm128(
    const float* __restrict__ A, int lda,
    const float* __restrict__ W,
    const float* __restrict__ bias,
    float* __restrict__ C, int ldc)
{
    __shared__ float As[8][132];
    __shared__ float Bs[8][128];

    const int tid = threadIdx.x;
    const int bm = blockIdx.y << 7;
    const int bn = blockIdx.x << 7;

    const int arow = tid >> 1;
    const int acol = (tid & 1) << 2;
    const int brow = tid >> 5;
    const int bcol = (tid & 31) << 2;
    const int tx = tid & 15;
    const int ty = tid >> 4;

    unsigned long long acc[8][4];
#pragma unroll
    for (int i = 0; i < 8; i++)
#pragma unroll
        for (int j = 0; j < 4; j++) acc[i][j] = 0ULL;

    const float* Ap = A + (size_t)(bm + arow) * lda + acol;
    const float* Wp = W + (size_t)brow * 1024 + bn + bcol;

    for (int k0 = 0; k0 < 1024; k0 += 8) {
        float4 av = *(const float4*)(Ap + k0);
        float4 bv = *(const float4*)(Wp + (size_t)k0 * 1024);
        As[acol + 0][arow] = av.x;
        As[acol + 1][arow] = av.y;
        As[acol + 2][arow] = av.z;
        As[acol + 3][arow] = av.w;
        *(float4*)&Bs[brow][bcol] = bv;
        __syncthreads();

#pragma unroll
        for (int k = 0; k < 8; k++) {
            float4 a0 = *(const float4*)&As[k][ty * 8];
            float4 a1 = *(const float4*)&As[k][ty * 8 + 4];
            float4 b0 = *(const float4*)&Bs[k][tx * 8];
            float4 b1 = *(const float4*)&Bs[k][tx * 8 + 4];
            unsigned long long bp[4] = { pk2(b0.x, b0.y), pk2(b0.z, b0.w),
                                         pk2(b1.x, b1.y), pk2(b1.z, b1.w) };
            float aa[8] = { a0.x, a0.y, a0.z, a0.w, a1.x, a1.y, a1.z, a1.w };
#pragma unroll
            for (int i = 0; i < 8; i++) {
                unsigned long long ap = pk2(aa[i], aa[i]);
#pragma unroll
                for (int j = 0; j < 4; j++) ffma2(acc[i][j], ap, bp[j]);
            }
        }
        __syncthreads();
    }

#pragma unroll
    for (int i = 0; i < 8; i++) {
        size_t row = (size_t)(bm + ty * 8 + i);
        float* Cp = C + row * (size_t)ldc + bn + tx * 8;
#pragma unroll
        for (int j = 0; j < 4; j++) {
            float2 v = *(float2*)&acc[i][j];
            v.x += bias[bn + tx * 8 + j * 2 + 0];
            v.y += bias[bn + tx * 8 + j * 2 + 1];
            *(float2*)(Cp + j * 2) = v;
        }
    }
}

// ============================================================
// Kernel 2/4: scores  S_s[bh][i][j] = sum_d q[i,d]*k[j,d]  (d=64)
// grid: (8 j-tiles, 8 i-tiles, 3*128). 128x128 tile, d in two 32-chunks,
// q/k transposed into smem ([d][row], pad 132 -> conflict-free).
// ============================================================
__global__ __launch_bounds__(256) void scores128()
{
    __shared__ float Qs[32][132];
    __shared__ float Ks[32][132];

    const int tid = threadIdx.x;
    const int z = blockIdx.z;
    const int s = z >> 7;
    const int bh = z & 127;
    const int b = bh >> 4;
    const int h = bh & 15;
    const int i0 = blockIdx.y << 7;
    const int j0 = blockIdx.x << 7;

    const float* qg = g_qkv[0][s];
    const float* kg = g_qkv[1][s];
    float* Sg = g_S[s][bh];

    const int lr = tid & 127;
    const int half = tid >> 7;
    const int tx = tid & 15;
    const int ty = tid >> 4;

    unsigned long long acc[8][4];
#pragma unroll
    for (int i = 0; i < 8; i++)
#pragma unroll
        for (int j = 0; j < 4; j++) acc[i][j] = 0ULL;

    const size_t qrow = (size_t)((b << 10) + i0 + lr) * 1024 + (h << 6);
    const size_t krow = (size_t)((b << 10) + j0 + lr) * 1024 + (h << 6);

    for (int d0 = 0; d0 < 64; d0 += 32) {
#pragma unroll
        for (int v = 0; v < 4; v++) {
            int d = (half << 4) + (v << 2);
            float4 qv = *(const float4*)(qg + qrow + d0 + d);
            float4 kv = *(const float4*)(kg + krow + d0 + d);
            Qs[d + 0][lr] = qv.x; Qs[d + 1][lr] = qv.y;
            Qs[d + 2][lr] = qv.z; Qs[d + 3][lr] = qv.w;
            Ks[d + 0][lr] = kv.x; Ks[d + 1][lr] = kv.y;
            Ks[d + 2][lr] = kv.z; Ks[d + 3][lr] = kv.w;
        }
        __syncthreads();

#pragma unroll
        for (int k = 0; k < 32; k++) {
            float4 a0 = *(const float4*)&Qs[k][ty * 8];
            float4 a1 = *(const float4*)&Qs[k][ty * 8 + 4];
            float4 b0 = *(const float4*)&Ks[k][tx * 8];
            float4 b1 = *(const float4*)&Ks[k][tx * 8 + 4];
            unsigned long long bp[4] = { pk2(b0.x, b0.y), pk2(b0.z, b0.w),
                                         pk2(b1.x, b1.y), pk2(b1.z, b1.w) };
            float aa[8] = { a0.x, a0.y, a0.z, a0.w, a1.x, a1.y, a1.z, a1.w };
#pragma unroll
            for (int i = 0; i < 8; i++) {
                unsigned long long ap = pk2(aa[i], aa[i]);
#pragma unroll
                for (int j = 0; j < 4; j++) ffma2(acc[i][j], ap, bp[j]);
            }
        }
        __syncthreads();
    }

#pragma unroll
    for (int i = 0; i < 8; i++) {
        float* Sp = Sg + (size_t)(i0 + ty * 8 + i) * 1024 + j0 + tx * 8;
#pragma unroll
        for (int j = 0; j < 4; j++) {
            *(float2*)(Sp + 2 * j) = *(float2*)&acc[i][j];
        }
    }
}

// ============================================================
// Kernel 3/4: fused softmax((S_a+S_b)*0.0625) @ V  -> g_O
// grid: (1, 32 q-tiles of 32 rows, 3*128). 256 threads.
// Thread t: row r = t>>3 (0..31), 8 output dims at cp=(t&7)*8.
// Key tiles of 64; online softmax; P staged via smem; V in smem.
// ============================================================
__global__ __launch_bounds__(256) void attn_pv()
{
    __shared__ float Vs[64][64];
    __shared__ float Ps[32][72];

    const int tid = threadIdx.x;
    const int z = blockIdx.z;
    const int o = z >> 7;          // output stream = V stream
    const int bh = z & 127;
    const int b = bh >> 4;
    const int h = bh & 15;
    const int i0 = blockIdx.y << 5;

    const int sa = (o == 0) ? 1 : 0;
    const int sb = (o == 2) ? 1 : 2;

    const int r = tid >> 3;
    const int cg = tid & 7;
    const int cp = cg << 3;

    const float* SaP = g_S[sa][bh] + (size_t)(i0 + r) * 1024;
    const float* SbP = g_S[sb][bh] + (size_t)(i0 + r) * 1024;
    const float* Vg  = g_qkv[2][o] + (size_t)(b << 10) * 1024 + (h << 6);

    float m = -1e30f, l = 0.f;
    unsigned long long acc[4] = {0ULL, 0ULL, 0ULL, 0ULL};

    for (int kt = 0; kt < 16; kt++) {
        const int kb = kt << 6;

        // load V tile (64 keys x 64 dims), coalesced
#pragma unroll
        for (int it = 0; it < 4; it++) {
            int idx = (tid << 2) + (it << 10);
            int vr = idx >> 6, vc = idx & 63;
            *(float4*)&Vs[vr][vc] = *(const float4*)(Vg + (size_t)(kb + vr) * 1024 + vc);
        }

        // logits + online softmax update
        float lg[8];
        float tmax = -1e30f;
#pragma unroll
        for (int u = 0; u < 8; u++) {
            int c = cg + (u << 3);
            float v = (SaP[kb + c] + SbP[kb + c]) * 0.0625f;
            lg[u] = v;
            tmax = fmaxf(tmax, v);
        }
#pragma unroll
        for (int off = 1; off < 8; off <<= 1)
            tmax = fmaxf(tmax, __shfl_xor_sync(0xffffffffu, tmax, off));

        float mnew = fmaxf(m, tmax);
        float f = __expf(m - mnew);      // m starts at -1e30 -> underflows to 0
        float p[8];
        float lsum = 0.f;
#pragma unroll
        for (int u = 0; u < 8; u++) {
            p[u] = __expf(lg[u] - mnew);
            lsum += p[u];
        }
#pragma unroll
        for (int off = 1; off < 8; off <<= 1)
            lsum += __shfl_xor_sync(0xffffffffu, lsum, off);

        l = l * f + lsum;
        m = mnew;
#pragma unroll
        for (int j = 0; j < 4; j++) {
            float2* a = reinterpret_cast<float2*>(&acc[j]);
            a->x *= f; a->y *= f;
        }
#pragma unroll
        for (int u = 0; u < 8; u++)
            Ps[r][cg + (u << 3)] = p[u];

        __syncthreads();

        // P @ V
#pragma unroll 2
        for (int kk = 0; kk < 64; kk++) {
            float pv = Ps[r][kk];
            unsigned long long pp = pk2(pv, pv);
            ulonglong2 v0 = *(const ulonglong2*)&Vs[kk][cp];
            ulonglong2 v1 = *(const ulonglong2*)&Vs[kk][cp + 4];
            ffma2(acc[0], pp, v0.x);
            ffma2(acc[1], pp, v0.y);
            ffma2(acc[2], pp, v1.x);
            ffma2(acc[3], pp, v1.y);
        }
        __syncthreads();
    }

    const float inv = 1.0f / l;
    float* Og = g_O[o] + (size_t)((b << 10) + i0 + r) * 1024 + (h << 6) + cp;
#pragma unroll
    for (int j = 0; j < 4; j++) {
        float2 a = *(float2*)&acc[j];
        *(float2*)(Og + 2 * j) = make_float2(a.x * inv, a.y * inv);
    }
}

// ============================================================
// Launch
// ============================================================
extern "C" void kernel_launch(void* const* d_in, const int* in_sizes, int n_in,
                              void* d_out, int out_size)
{
    const float* x  = (const float*)d_in[0];
    const float* Wq = (const float*)d_in[1];
    const float* bq = (const float*)d_in[2];
    const float* Wk = (const float*)d_in[3];
    const float* bk = (const float*)d_in[4];
    const float* Wv = (const float*)d_in[5];
    const float* bv = (const float*)d_in[6];
    const float* Wo = (const float*)d_in[7];
    const float* bo = (const float*)d_in[8];
    float* out = (float*)d_out;

    float* qkv = nullptr;
    float* obuf = nullptr;
    cudaGetSymbolAddress((void**)&qkv, g_qkv);
    cudaGetSymbolAddress((void**)&obuf, g_O);

    const float* Ws[3] = { Wq, Wk, Wv };
    const float* bs[3] = { bq, bk, bv };

    dim3 gProj(8, 64);

    // 1) QKV projections: 9 GEMMs (p = q/k/v, s = stream)
    for (int p = 0; p < 3; p++)
        for (int s = 0; s < 3; s++)
            sgemm128<<<gProj, 256>>>(x + s * 1024, 3072, Ws[p], bs[p],
                                     qkv + ((size_t)p * 3 + s) * 8388608ULL, 1024);

    // 2) Score matrices (each computed once, consumed twice)
    scores128<<<dim3(8, 8, 384), 256>>>();

    // 3) Dual-softmax attention + PV
    attn_pv<<<dim3(1, 32, 384), 256>>>();

    // 4) Output projection into (B, L, 3, D) layout
    for (int s = 0; s < 3; s++)
        sgemm128<<<gProj, 256>>>(obuf + (size_t)s * 8388608ULL, 1024, Wo, bo,
                                 out + s * 1024, 3072);
}

// round 2
// speedup vs baseline: 1.3973x; 1.3973x over previous
#include <cuda_runtime.h>
#include <cstdint>

// x: (8, 1024, 3, 1024) fp32; streams s=0(H),1(T),2(R)
// Pipeline:
//  1) sgemm128 x9 : q/k/v projections -> g_qkv[p][s]
//  2) scores128   : g_S[s][bh] = (q_s . k_s) * 0.0625  (pre-scaled)
//  3) softmax_dual: g_P[o][bh] = softmax(S_a + S_b) (normalized)
//  4) pv128       : g_O[o] = P @ V
//  5) sgemm128 x3 : output projection + bo -> d_out (B,L,3,D)

__device__ float g_qkv[3][3][8388608];   // [q/k/v][s][8192*1024]
__device__ float g_S[3][128][1048576];   // [s][bh][1024*1024] scaled scores
__device__ float g_P[3][128][1048576];   // [o][bh] normalized probabilities
__device__ float g_O[3][8388608];        // [o][8192*1024]

typedef unsigned long long u64;

__device__ __forceinline__ u64 pk2(float lo, float hi) {
    u64 r; asm("mov.b64 %0, {%1, %2};" : "=l"(r) : "f"(lo), "f"(hi)); return r;
}
__device__ __forceinline__ void ffma2(u64& d, u64 a, u64 b) {
    asm("fma.rn.f32x2 %0, %1, %2, %0;" : "+l"(d) : "l"(a), "l"(b));
}

// ============================================================
// Kernel 1/5: SGEMM  C = A(M=8192 x K=1024) * W(1024x1024) + bias
// 128x128 tile, BK=8, 256 thr, 8x8/thread. Double-buffered smem.
// A-pairs packed along M (direct LDS.128 from transposed As);
// B duplicated in smem -> broadcast operand via conflict-free LDS.64.
// ============================================================
__global__ __launch_bounds__(256, 2) void sgemm128(
    const float* __restrict__ A, int lda,
    const float* __restrict__ W,
    const float* __restrict__ bias,
    float* __restrict__ C, int ldc)
{
    __shared__ __align__(16) float As[2][8][132];
    __shared__ __align__(16) float Bs2[2][8][256];   // duplicated pairs

    const int tid = threadIdx.x;
    const int bm = blockIdx.y << 7;
    const int bn = blockIdx.x << 7;

    const int arow = tid >> 1, acol = (tid & 1) << 2;   // A staging
    const int brow = tid >> 5, bc0 = tid & 31;          // B staging (strided cols)
    const int tx = tid & 15, ty = tid >> 4;             // compute mapping

    const float* Ap = A + (size_t)(bm + arow) * lda + acol;
    const float* Wp = W + (size_t)brow * 1024 + bn + bc0;

    u64 acc[4][8];
#pragma unroll
    for (int i = 0; i < 4; i++)
#pragma unroll
        for (int u = 0; u < 8; u++) acc[i][u] = 0ULL;

    // prologue: stage tile 0
    {
        float4 av = *(const float4*)(Ap);
        As[0][acol + 0][arow] = av.x; As[0][acol + 1][arow] = av.y;
        As[0][acol + 2][arow] = av.z; As[0][acol + 3][arow] = av.w;
#pragma unroll
        for (int u = 0; u < 4; u++) {
            float v = Wp[32 * u];
            *(float2*)&Bs2[0][brow][2 * (bc0 + 32 * u)] = make_float2(v, v);
        }
    }
    __syncthreads();

#pragma unroll 1
    for (int kt = 1; kt <= 128; kt++) {
        const int buf = (kt - 1) & 1;
        float4 av; float bv[4];
        if (kt < 128) {
            av = *(const float4*)(Ap + kt * 8);
#pragma unroll
            for (int u = 0; u < 4; u++)
                bv[u] = Wp[(size_t)kt * 8192 + 32 * u];
        }
#pragma unroll
        for (int k = 0; k < 8; k++) {
            ulonglong2 a01 = *(const ulonglong2*)&As[buf][k][ty * 8];
            ulonglong2 a23 = *(const ulonglong2*)&As[buf][k][ty * 8 + 4];
            u64 ap[4] = { a01.x, a01.y, a23.x, a23.y };
            u64 bp[8];
#pragma unroll
            for (int u = 0; u < 8; u++)
                bp[u] = *(const u64*)&Bs2[buf][k][2 * (tx + 16 * u)];
#pragma unroll
            for (int i = 0; i < 4; i++)
#pragma unroll
                for (int u = 0; u < 8; u++)
                    ffma2(acc[i][u], ap[i], bp[u]);
        }
        if (kt < 128) {
            const int nb = buf ^ 1;
            As[nb][acol + 0][arow] = av.x; As[nb][acol + 1][arow] = av.y;
            As[nb][acol + 2][arow] = av.z; As[nb][acol + 3][arow] = av.w;
#pragma unroll
            for (int u = 0; u < 4; u++)
                *(float2*)&Bs2[nb][brow][2 * (bc0 + 32 * u)] = make_float2(bv[u], bv[u]);
        }
        __syncthreads();
    }

    float bb[8];
#pragma unroll
    for (int u = 0; u < 8; u++) bb[u] = bias[bn + tx + 16 * u];
#pragma unroll
    for (int i = 0; i < 4; i++) {
#pragma unroll
        for (int hh = 0; hh < 2; hh++) {
            size_t row = (size_t)(bm + ty * 8 + 2 * i + hh);
            float* Cp = C + row * (size_t)ldc + bn + tx;
#pragma unroll
            for (int u = 0; u < 8; u++) {
                float2 v2 = *(float2*)&acc[i][u];
                Cp[16 * u] = (hh ? v2.y : v2.x) + bb[u];
            }
        }
    }
}

// ============================================================
// Kernel 2/5: scores  S_s[bh][i][j] = (q . k) * 0.0625  (d=64)
// ============================================================
__global__ __launch_bounds__(256) void scores128()
{
    __shared__ float Qs[32][132];
    __shared__ float Ks[32][132];

    const int tid = threadIdx.x;
    const int z = blockIdx.z;
    const int s = z >> 7;
    const int bh = z & 127;
    const int b = bh >> 4;
    const int h = bh & 15;
    const int i0 = blockIdx.y << 7;
    const int j0 = blockIdx.x << 7;

    const float* qg = g_qkv[0][s];
    const float* kg = g_qkv[1][s];
    float* Sg = g_S[s][bh];

    const int lr = tid & 127;
    const int half = tid >> 7;
    const int tx = tid & 15;
    const int ty = tid >> 4;

    u64 acc[8][4];
#pragma unroll
    for (int i = 0; i < 8; i++)
#pragma unroll
        for (int j = 0; j < 4; j++) acc[i][j] = 0ULL;

    const size_t qrow = (size_t)((b << 10) + i0 + lr) * 1024 + (h << 6);
    const size_t krow = (size_t)((b << 10) + j0 + lr) * 1024 + (h << 6);

    for (int d0 = 0; d0 < 64; d0 += 32) {
#pragma unroll
        for (int v = 0; v < 4; v++) {
            int d = (half << 4) + (v << 2);
            float4 qv = *(const float4*)(qg + qrow + d0 + d);
            float4 kv = *(const float4*)(kg + krow + d0 + d);
            Qs[d + 0][lr] = qv.x; Qs[d + 1][lr] = qv.y;
            Qs[d + 2][lr] = qv.z; Qs[d + 3][lr] = qv.w;
            Ks[d + 0][lr] = kv.x; Ks[d + 1][lr] = kv.y;
            Ks[d + 2][lr] = kv.z; Ks[d + 3][lr] = kv.w;
        }
        __syncthreads();

#pragma unroll
        for (int k = 0; k < 32; k++) {
            float4 a0 = *(const float4*)&Qs[k][ty * 8];
            float4 a1 = *(const float4*)&Qs[k][ty * 8 + 4];
            float4 b0 = *(const float4*)&Ks[k][tx * 8];
            float4 b1 = *(const float4*)&Ks[k][tx * 8 + 4];
            u64 bp[4] = { pk2(b0.x, b0.y), pk2(b0.z, b0.w),
                          pk2(b1.x, b1.y), pk2(b1.z, b1.w) };
            float aa[8] = { a0.x, a0.y, a0.z, a0.w, a1.x, a1.y, a1.z, a1.w };
#pragma unroll
            for (int i = 0; i < 8; i++) {
                u64 ap = pk2(aa[i], aa[i]);
#pragma unroll
                for (int j = 0; j < 4; j++) ffma2(acc[i][j], ap, bp[j]);
            }
        }
        __syncthreads();
    }

#pragma unroll
    for (int i = 0; i < 8; i++) {
        float* Sp = Sg + (size_t)(i0 + ty * 8 + i) * 1024 + j0 + tx * 8;
#pragma unroll
        for (int j = 0; j < 4; j++) {
            float2 v = *(float2*)&acc[i][j];
            v.x *= 0.0625f; v.y *= 0.0625f;
            *(float2*)(Sp + 2 * j) = v;
        }
    }
}

// ============================================================
// Kernel 3/5: softmax_dual  P_o[bh][row] = softmax(S_a + S_b)
// one warp per row (1024 cols = 32 floats/lane), normalized write.
// grid (128 rowblocks, 128 bh, 3 o), 256 thr.
// ============================================================
__global__ __launch_bounds__(256) void softmax_dual()
{
    const int o = blockIdx.z;
    const int bh = blockIdx.y;
    const int tid = threadIdx.x;
    const int warp = tid >> 5, lane = tid & 31;
    const int row = (blockIdx.x << 3) + warp;

    const int sa = (o == 0) ? 1 : 0;
    const int sb = (o == 2) ? 1 : 2;

    const float4* Sa4 = (const float4*)(g_S[sa][bh] + (size_t)row * 1024);
    const float4* Sb4 = (const float4*)(g_S[sb][bh] + (size_t)row * 1024);
    float4* P4 = (float4*)(g_P[o][bh] + (size_t)row * 1024);

    float4 v[8];
    float mx = -1e30f;
#pragma unroll
    for (int q = 0; q < 8; q++) {
        float4 a = Sa4[lane + 32 * q];
        float4 b = Sb4[lane + 32 * q];
        v[q].x = a.x + b.x; v[q].y = a.y + b.y;
        v[q].z = a.z + b.z; v[q].w = a.w + b.w;
        mx = fmaxf(mx, fmaxf(fmaxf(v[q].x, v[q].y), fmaxf(v[q].z, v[q].w)));
    }
#pragma unroll
    for (int off = 16; off >= 1; off >>= 1)
        mx = fmaxf(mx, __shfl_xor_sync(0xffffffffu, mx, off));

    float s = 0.f;
#pragma unroll
    for (int q = 0; q < 8; q++) {
        v[q].x = __expf(v[q].x - mx); v[q].y = __expf(v[q].y - mx);
        v[q].z = __expf(v[q].z - mx); v[q].w = __expf(v[q].w - mx);
        s += (v[q].x + v[q].y) + (v[q].z + v[q].w);
    }
#pragma unroll
    for (int off = 16; off >= 1; off >>= 1)
        s += __shfl_xor_sync(0xffffffffu, s, off);

    const float inv = 1.0f / s;
#pragma unroll
    for (int q = 0; q < 8; q++) {
        float4 w = v[q];
        w.x *= inv; w.y *= inv; w.z *= inv; w.w *= inv;
        P4[lane + 32 * q] = w;
    }
}

// ============================================================
// Kernel 4/5: pv128  O[1024,64] = P[1024,1024] @ V[1024,64]  per (o,bh)
// tile 128x64, BK=16, 256 thr, 8x4/thread, double-buffered,
// same packed-pair + dup-B layout as sgemm.
// grid (8 mtiles, 128 bh, 3 o)
// ============================================================
__global__ __launch_bounds__(256) void pv128()
{
    __shared__ __align__(16) float Ps[2][16][132];
    __shared__ __align__(16) float Vs2[2][16][128];   // duplicated pairs (64 cols)

    const int tid = threadIdx.x;
    const int o = blockIdx.z;
    const int bh = blockIdx.y;
    const int b = bh >> 4, h = bh & 15;
    const int i0 = blockIdx.x << 7;

    const float* P = g_P[o][bh];
    const float* Vg = g_qkv[2][o] + ((size_t)(b << 10)) * 1024 + (h << 6);

    const int pr = tid >> 1, pc0 = (tid & 1) << 3;   // P staging: 128 x 16
    const int vrow = tid >> 4, vc0 = tid & 15;        // V staging: 16 x 64
    const int tx = tid & 15, ty = tid >> 4;           // compute: cols tx+16u (u<4)

    const float* Pp = P + (size_t)(i0 + pr) * 1024 + pc0;
    const float* Vp = Vg + (size_t)vrow * 1024 + vc0;

    u64 acc[4][4];
#pragma unroll
    for (int i = 0; i < 4; i++)
#pragma unroll
        for (int u = 0; u < 4; u++) acc[i][u] = 0ULL;

    // prologue
    {
        float4 p0 = *(const float4*)(Pp);
        float4 p1 = *(const float4*)(Pp + 4);
        Ps[0][pc0 + 0][pr] = p0.x; Ps[0][pc0 + 1][pr] = p0.y;
        Ps[0][pc0 + 2][pr] = p0.z; Ps[0][pc0 + 3][pr] = p0.w;
        Ps[0][pc0 + 4][pr] = p1.x; Ps[0][pc0 + 5][pr] = p1.y;
        Ps[0][pc0 + 6][pr] = p1.z; Ps[0][pc0 + 7][pr] = p1.w;
#pragma unroll
        for (int u = 0; u < 4; u++) {
            float vv = Vp[16 * u];
            *(float2*)&Vs2[0][vrow][2 * (vc0 + 16 * u)] = make_float2(vv, vv);
        }
    }
    __syncthreads();

#pragma unroll 1
    for (int kt = 1; kt <= 64; kt++) {
        const int buf = (kt - 1) & 1;
        float4 p0, p1; float vv[4];
        if (kt < 64) {
            p0 = *(const float4*)(Pp + kt * 16);
            p1 = *(const float4*)(Pp + kt * 16 + 4);
#pragma unroll
            for (int u = 0; u < 4; u++)
                vv[u] = Vp[(size_t)kt * 16384 + 16 * u];
        }
#pragma unroll
        for (int k = 0; k < 16; k++) {
            ulonglong2 a01 = *(const ulonglong2*)&Ps[buf][k][ty * 8];
            ulonglong2 a23 = *(const ulonglong2*)&Ps[buf][k][ty * 8 + 4];
            u64 ap[4] = { a01.x, a01.y, a23.x, a23.y };
            u64 bp[4];
#pragma unroll
            for (int u = 0; u < 4; u++)
                bp[u] = *(const u64*)&Vs2[buf][k][2 * (tx + 16 * u)];
#pragma unroll
            for (int i = 0; i < 4; i++)
#pragma unroll
                for (int u = 0; u < 4; u++)
                    ffma2(acc[i][u], ap[i], bp[u]);
        }
        if (kt < 64) {
            const int nb = buf ^ 1;
            Ps[nb][pc0 + 0][pr] = p0.x; Ps[nb][pc0 + 1][pr] = p0.y;
            Ps[nb][pc0 + 2][pr] = p0.z; Ps[nb][pc0 + 3][pr] = p0.w;
            Ps[nb][pc0 + 4][pr] = p1.x; Ps[nb][pc0 + 5][pr] = p1.y;
            Ps[nb][pc0 + 6][pr] = p1.z; Ps[nb][pc0 + 7][pr] = p1.w;
#pragma unroll
            for (int u = 0; u < 4; u++)
                *(float2*)&Vs2[nb][vrow][2 * (vc0 + 16 * u)] = make_float2(vv[u], vv[u]);
        }
        __syncthreads();
    }

#pragma unroll
    for (int i = 0; i < 4; i++) {
#pragma unroll
        for (int hh = 0; hh < 2; hh++) {
            size_t m = (size_t)((b << 10) + i0 + ty * 8 + 2 * i + hh);
            float* Op = g_O[o] + m * 1024 + (h << 6) + tx;
#pragma unroll
            for (int u = 0; u < 4; u++) {
                float2 v2 = *(float2*)&acc[i][u];
                Op[16 * u] = hh ? v2.y : v2.x;
            }
        }
    }
}

// ============================================================
// Launch
// ============================================================
extern "C" void kernel_launch(void* const* d_in, const int* in_sizes, int n_in,
                              void* d_out, int out_size)
{
    const float* x  = (const float*)d_in[0];
    const float* Wq = (const float*)d_in[1];
    const float* bq = (const float*)d_in[2];
    const float* Wk = (const float*)d_in[3];
    const float* bk = (const float*)d_in[4];
    const float* Wv = (const float*)d_in[5];
    const float* bv = (const float*)d_in[6];
    const float* Wo = (const float*)d_in[7];
    const float* bo = (const float*)d_in[8];
    float* out = (float*)d_out;

    float* qkv = nullptr;
    float* obuf = nullptr;
    cudaGetSymbolAddress((void**)&qkv, g_qkv);
    cudaGetSymbolAddress((void**)&obuf, g_O);

    const float* Ws[3] = { Wq, Wk, Wv };
    const float* bs[3] = { bq, bk, bv };

    dim3 gProj(8, 64);

    // 1) QKV projections
    for (int p = 0; p < 3; p++)
        for (int s = 0; s < 3; s++)
            sgemm128<<<gProj, 256>>>(x + s * 1024, 3072, Ws[p], bs[p],
                                     qkv + ((size_t)p * 3 + s) * 8388608ULL, 1024);

    // 2) Scaled score matrices (computed once, consumed twice)
    scores128<<<dim3(8, 8, 384), 256>>>();

    // 3) Dual softmax -> normalized P
    softmax_dual<<<dim3(128, 128, 3), 256>>>();

    // 4) P @ V
    pv128<<<dim3(8, 128, 3), 256>>>();

    // 5) Output projection into (B, L, 3, D)
    for (int s = 0; s < 3; s++)
        sgemm128<<<gProj, 256>>>(obuf + (size_t)s * 8388608ULL, 1024, Wo, bo,
                                 out + s * 1024, 3072);
}

// round 4
// speedup vs baseline: 2.2283x; 1.5947x over previous
#include <cuda_runtime.h>
#include <cuda_bf16.h>
#include <cstdint>

typedef __nv_bfloat16 bf16;
typedef unsigned int u32;

#define NN 8388608ULL      // 8192*1024
#define NW 1048576ULL      // 1024*1024

// ---------------- global scratch ----------------
__device__ bf16 g_Ah[3][NN], g_Al[3][NN];        // x split
__device__ bf16 g_Qh[3][NN], g_Ql[3][NN];
__device__ bf16 g_Kh[3][NN], g_Kl[3][NN];
__device__ bf16 g_Vh[3][NN], g_Vl[3][NN];
__device__ bf16 g_AOh[3][NN], g_AOl[3][NN];      // attention out split
__device__ bf16 g_Ph[3][128][NW], g_Pl[3][128][NW];
__device__ float g_S[3][128][NW];                // scaled scores fp32
__device__ bf16 g_Wth[4][NW], g_Wtl[4][NW];      // W^T splits [q,k,v,o]

// ---------------- PTX helpers ----------------
__device__ __forceinline__ u32 smem_u32(const void* p) {
    u32 a;
    asm("{ .reg .u64 t; cvta.to.shared.u64 t, %1; cvt.u32.u64 %0, t; }" : "=r"(a) : "l"(p));
    return a;
}
__device__ __forceinline__ void cp16(u32 d, const void* s) {
    asm volatile("cp.async.cg.shared.global [%0], [%1], 16;" :: "r"(d), "l"(s));
}
__device__ __forceinline__ void cpcommit() { asm volatile("cp.async.commit_group;"); }
template<int N> __device__ __forceinline__ void cpwait() {
    asm volatile("cp.async.wait_group %0;" :: "n"(N));
}
__device__ __forceinline__ void ldm4(u32* r, u32 a) {
    asm volatile("ldmatrix.sync.aligned.m8n8.x4.shared.b16 {%0,%1,%2,%3}, [%4];"
                 : "=r"(r[0]), "=r"(r[1]), "=r"(r[2]), "=r"(r[3]) : "r"(a));
}
__device__ __forceinline__ void ldm4t(u32* r, u32 a) {
    asm volatile("ldmatrix.sync.aligned.m8n8.x4.trans.shared.b16 {%0,%1,%2,%3}, [%4];"
                 : "=r"(r[0]), "=r"(r[1]), "=r"(r[2]), "=r"(r[3]) : "r"(a));
}
__device__ __forceinline__ void mma_bf(float* c, const u32* a, u32 b0, u32 b1) {
    asm volatile(
        "mma.sync.aligned.m16n8k16.row.col.f32.bf16.bf16.f32 "
        "{%0,%1,%2,%3}, {%4,%5,%6,%7}, {%8,%9}, {%0,%1,%2,%3};"
        : "+f"(c[0]), "+f"(c[1]), "+f"(c[2]), "+f"(c[3])
        : "r"(a[0]), "r"(a[1]), "r"(a[2]), "r"(a[3]), "r"(b0), "r"(b1));
}
__device__ __forceinline__ void wsplit2(bf16* H, bf16* L, size_t off, float v0, float v1) {
    bf16 h0 = __float2bfloat16(v0); bf16 l0 = __float2bfloat16(v0 - __bfloat162float(h0));
    bf16 h1 = __float2bfloat16(v1); bf16 l1 = __float2bfloat16(v1 - __bfloat162float(h1));
    __nv_bfloat162 hh; hh.x = h0; hh.y = h1;
    __nv_bfloat162 ll; ll.x = l0; ll.y = l1;
    *(__nv_bfloat162*)(H + off) = hh;
    *(__nv_bfloat162*)(L + off) = ll;
}
__device__ __forceinline__ u32 packbf(float a, float b) {
    __nv_bfloat162 t; t.x = __float2bfloat16(a); t.y = __float2bfloat16(b);
    return *(u32*)&t;
}

// ============================================================
// Shared GEMM core: 128x128 CTA tile, BK=32, 256 thr, 8 warps (2m x 4n),
// warp tile 64x32, bf16 hi/lo 3-term split, cp.async double buffer.
// smem row stride 80B (40 elems) -> conflict-free ldmatrix.
// ============================================================
#define GMAT 10240        // 128*80
#define GBUF 40960        // 4 matrices
#define GEMM_SMEM 81920   // 2 buffers

__device__ __forceinline__ void stage_g(u32 sm,
    const bf16* __restrict__ Ah, const bf16* __restrict__ Al, int lda,
    const bf16* __restrict__ Bh, const bf16* __restrict__ Bl, int ldb,
    int k0, int tid)
{
    const int r = tid >> 2, cc = tid & 3;
    const u32 so = r * 80 + cc * 16;
    const int co = k0 + cc * 8;
    cp16(sm + so,                 Ah + (size_t)r * lda + co);
    cp16(sm + so + 5120,          Ah + (size_t)(r + 64) * lda + co);
    cp16(sm + GMAT + so,          Al + (size_t)r * lda + co);
    cp16(sm + GMAT + so + 5120,   Al + (size_t)(r + 64) * lda + co);
    cp16(sm + 2*GMAT + so,        Bh + (size_t)r * ldb + co);
    cp16(sm + 2*GMAT + so + 5120, Bh + (size_t)(r + 64) * ldb + co);
    cp16(sm + 3*GMAT + so,        Bl + (size_t)r * ldb + co);
    cp16(sm + 3*GMAT + so + 5120, Bl + (size_t)(r + 64) * ldb + co);
}

__device__ __forceinline__ void gemm_core(u32 sm,
    const bf16* __restrict__ Ah, const bf16* __restrict__ Al, int lda,
    const bf16* __restrict__ Bh, const bf16* __restrict__ Bl, int ldb,
    int nk, float c[4][4][4])
{
    const int tid = threadIdx.x, wid = tid >> 5, lane = tid & 31;
    const int wm = wid >> 2, wn = wid & 3;
    const int lr = lane & 15, lc = lane >> 4;

    stage_g(sm, Ah, Al, lda, Bh, Bl, ldb, 0, tid);
    cpcommit();

#pragma unroll 1
    for (int kt = 0; kt < nk; kt++) {
        if (kt + 1 < nk) {
            stage_g(sm + ((kt + 1) & 1) * GBUF, Ah, Al, lda, Bh, Bl, ldb, (kt + 1) * 32, tid);
            cpcommit();
            cpwait<1>();
        } else {
            cpwait<0>();
        }
        __syncthreads();
        const u32 base = sm + (kt & 1) * GBUF;
#pragma unroll
        for (int ks = 0; ks < 2; ks++) {
            u32 ah[4][4], al[4][4], bh[2][4], bl[2][4];
            const u32 aoff = base + (wm * 64 + lr) * 80 + ks * 32 + lc * 16;
#pragma unroll
            for (int mf = 0; mf < 4; mf++) {
                ldm4(ah[mf], aoff + mf * 1280);
                ldm4(al[mf], aoff + mf * 1280 + GMAT);
            }
            const u32 boff = base + 2 * GMAT + (wn * 32 + lr) * 80 + ks * 32 + lc * 16;
#pragma unroll
            for (int g = 0; g < 2; g++) {
                ldm4(bh[g], boff + g * 1280);
                ldm4(bl[g], boff + g * 1280 + GMAT);
            }
#pragma unroll
            for (int mf = 0; mf < 4; mf++)
#pragma unroll
                for (int nf = 0; nf < 4; nf++) {
                    const int g = nf >> 1, od = nf & 1;
                    mma_bf(c[mf][nf], ah[mf], bh[g][od], bh[g][od + 2]);
                    mma_bf(c[mf][nf], al[mf], bh[g][od], bh[g][od + 2]);
                    mma_bf(c[mf][nf], ah[mf], bl[g][od], bl[g][od + 2]);
                }
        }
        __syncthreads();
    }
}

// ============================================================
// hgemm_nk: C[8192,1024] = A @ B^T + bias (A,B k-major splits)
// out: fp32 strided and/or bf16 split
// ============================================================
__global__ __launch_bounds__(256) void hgemm_nk(
    const bf16* __restrict__ Ah, const bf16* __restrict__ Al,
    const bf16* __restrict__ Bh, const bf16* __restrict__ Bl,
    const float* __restrict__ bias,
    float* __restrict__ outF, int ldc,
    bf16* __restrict__ outH, bf16* __restrict__ outL)
{
    extern __shared__ __align__(16) char smraw[];
    const u32 sm = smem_u32(smraw);
    const int bm = blockIdx.y << 7, bn = blockIdx.x << 7;

    float c[4][4][4];
#pragma unroll
    for (int i = 0; i < 4; i++)
#pragma unroll
        for (int j = 0; j < 4; j++)
#pragma unroll
            for (int k = 0; k < 4; k++) c[i][j][k] = 0.f;

    gemm_core(sm, Ah + (size_t)bm * 1024, Al + (size_t)bm * 1024, 1024,
              Bh + (size_t)bn * 1024, Bl + (size_t)bn * 1024, 1024, 32, c);

    const int wid = threadIdx.x >> 5, lane = threadIdx.x & 31;
    const int wm = wid >> 2, wn = wid & 3;
    const int rbase = bm + wm * 64 + (lane >> 2);
    const int cbase = bn + wn * 32 + 2 * (lane & 3);
#pragma unroll
    for (int mf = 0; mf < 4; mf++)
#pragma unroll
        for (int nf = 0; nf < 4; nf++) {
            const int col = cbase + nf * 8;
            const float b0 = bias[col], b1 = bias[col + 1];
            const float v0 = c[mf][nf][0] + b0, v1 = c[mf][nf][1] + b1;
            const float v2 = c[mf][nf][2] + b0, v3 = c[mf][nf][3] + b1;
            const int row = rbase + mf * 16;
            if (outF) {
                *(float2*)(outF + (size_t)row * ldc + col) = make_float2(v0, v1);
                *(float2*)(outF + (size_t)(row + 8) * ldc + col) = make_float2(v2, v3);
            }
            if (outH) {
                wsplit2(outH, outL, (size_t)row * 1024 + col, v0, v1);
                wsplit2(outH, outL, (size_t)(row + 8) * 1024 + col, v2, v3);
            }
        }
}

// ============================================================
// hscores: S_s[bh] = (q.k^T)*0.0625, K=64 (nk=2)
// grid (8 j, 8 i, 384)
// ============================================================
__global__ __launch_bounds__(256) void hscores()
{
    extern __shared__ __align__(16) char smraw[];
    const u32 sm = smem_u32(smraw);
    const int z = blockIdx.z;
    const int s = z >> 7, bh = z & 127, b = bh >> 4, h = bh & 15;
    const int i0 = blockIdx.y << 7, j0 = blockIdx.x << 7;

    const size_t qo = (size_t)((b << 10) + i0) * 1024 + (h << 6);
    const size_t ko = (size_t)((b << 10) + j0) * 1024 + (h << 6);

    float c[4][4][4];
#pragma unroll
    for (int i = 0; i < 4; i++)
#pragma unroll
        for (int j = 0; j < 4; j++)
#pragma unroll
            for (int k = 0; k < 4; k++) c[i][j][k] = 0.f;

    gemm_core(sm, g_Qh[s] + qo, g_Ql[s] + qo, 1024,
              g_Kh[s] + ko, g_Kl[s] + ko, 1024, 2, c);

    const int wid = threadIdx.x >> 5, lane = threadIdx.x & 31;
    const int wm = wid >> 2, wn = wid & 3;
    const int rbase = i0 + wm * 64 + (lane >> 2);
    const int cbase = j0 + wn * 32 + 2 * (lane & 3);
    float* Sg = g_S[s][bh];
#pragma unroll
    for (int mf = 0; mf < 4; mf++)
#pragma unroll
        for (int nf = 0; nf < 4; nf++) {
            const int row = rbase + mf * 16, col = cbase + nf * 8;
            *(float2*)(Sg + (size_t)row * 1024 + col) =
                make_float2(c[mf][nf][0] * 0.0625f, c[mf][nf][1] * 0.0625f);
            *(float2*)(Sg + (size_t)(row + 8) * 1024 + col) =
                make_float2(c[mf][nf][2] * 0.0625f, c[mf][nf][3] * 0.0625f);
        }
}

// ============================================================
// softmax_dual: P_o = softmax(S_a + S_b), writes bf16 hi/lo split
// grid (128, 128 bh, 3 o), 256 thr, warp per row
// ============================================================
__global__ __launch_bounds__(256) void softmax_dual()
{
    const int o = blockIdx.z, bh = blockIdx.y;
    const int tid = threadIdx.x;
    const int warp = tid >> 5, lane = tid & 31;
    const int row = (blockIdx.x << 3) + warp;

    const int sa = (o == 0) ? 1 : 0;
    const int sb = (o == 2) ? 1 : 2;

    const float4* Sa4 = (const float4*)(g_S[sa][bh] + (size_t)row * 1024);
    const float4* Sb4 = (const float4*)(g_S[sb][bh] + (size_t)row * 1024);

    float4 v[8];
    float mx = -1e30f;
#pragma unroll
    for (int q = 0; q < 8; q++) {
        float4 a = Sa4[lane + 32 * q];
        float4 b = Sb4[lane + 32 * q];
        v[q].x = a.x + b.x; v[q].y = a.y + b.y;
        v[q].z = a.z + b.z; v[q].w = a.w + b.w;
        mx = fmaxf(mx, fmaxf(fmaxf(v[q].x, v[q].y), fmaxf(v[q].z, v[q].w)));
    }
#pragma unroll
    for (int off = 16; off >= 1; off >>= 1)
        mx = fmaxf(mx, __shfl_xor_sync(0xffffffffu, mx, off));

    float sum = 0.f;
#pragma unroll
    for (int q = 0; q < 8; q++) {
        v[q].x = __expf(v[q].x - mx); v[q].y = __expf(v[q].y - mx);
        v[q].z = __expf(v[q].z - mx); v[q].w = __expf(v[q].w - mx);
        sum += (v[q].x + v[q].y) + (v[q].z + v[q].w);
    }
#pragma unroll
    for (int off = 16; off >= 1; off >>= 1)
        sum += __shfl_xor_sync(0xffffffffu, sum, off);

    const float inv = 1.0f / sum;
    bf16* Ph = g_Ph[o][bh] + (size_t)row * 1024;
    bf16* Pl = g_Pl[o][bh] + (size_t)row * 1024;
#pragma unroll
    for (int q = 0; q < 8; q++) {
        float p0 = v[q].x * inv, p1 = v[q].y * inv, p2 = v[q].z * inv, p3 = v[q].w * inv;
        bf16 h0 = __float2bfloat16(p0); float l0 = p0 - __bfloat162float(h0);
        bf16 h1 = __float2bfloat16(p1); float l1 = p1 - __bfloat162float(h1);
        bf16 h2 = __float2bfloat16(p2); float l2 = p2 - __bfloat162float(h2);
        bf16 h3 = __float2bfloat16(p3); float l3 = p3 - __bfloat162float(h3);
        const int col = 4 * (lane + 32 * q);
        uint2 hv, lv;
        __nv_bfloat162 t01; t01.x = h0; t01.y = h1;
        __nv_bfloat162 t23; t23.x = h2; t23.y = h3;
        hv.x = *(u32*)&t01; hv.y = *(u32*)&t23;
        lv.x = packbf(l0, l1); lv.y = packbf(l2, l3);
        *(uint2*)(Ph + col) = hv;
        *(uint2*)(Pl + col) = lv;
    }
}

// ============================================================
// hpv: AO = P @ V per (o,bh). CTA 128x64, BK=32, 8 warps (4m x 2n),
// warp tile 32x32. V loaded [k][d] with ldmatrix.trans.
// grid (8 m-tiles, 128 bh, 3 o)
// ============================================================
#define PMAT 10240
#define VMAT 4608         // 32*144
#define PVBUF 29696       // 2*PMAT + 2*VMAT
#define PV_SMEM 59392

__global__ __launch_bounds__(256) void hpv()
{
    extern __shared__ __align__(16) char smraw[];
    const u32 sm = smem_u32(smraw);
    const int tid = threadIdx.x, wid = tid >> 5, lane = tid & 31;
    const int o = blockIdx.z, bh = blockIdx.y;
    const int b = bh >> 4, h = bh & 15;
    const int i0 = blockIdx.x << 7;
    const int wm = wid & 3, wn = wid >> 2;
    const int lr = lane & 15, lc = lane >> 4;

    const bf16* Ph = g_Ph[o][bh] + (size_t)i0 * 1024;
    const bf16* Pl = g_Pl[o][bh] + (size_t)i0 * 1024;
    const bf16* Vh = g_Vh[o] + ((size_t)(b << 10)) * 1024 + (h << 6);
    const bf16* Vl = g_Vl[o] + ((size_t)(b << 10)) * 1024 + (h << 6);

    float c[2][4][4];
#pragma unroll
    for (int i = 0; i < 2; i++)
#pragma unroll
        for (int j = 0; j < 4; j++)
#pragma unroll
            for (int k = 0; k < 4; k++) c[i][j][k] = 0.f;

    // staging lambda-equivalent
    const int ar = tid >> 2, ac = tid & 3;
    const u32 aso = ar * 80 + ac * 16;
    const int vr = tid >> 3, vc = tid & 7;
    const u32 vso = vr * 144 + vc * 16;

    // prologue k0=0
    {
        cp16(sm + aso,                 Ph + (size_t)ar * 1024 + ac * 8);
        cp16(sm + aso + 5120,          Ph + (size_t)(ar + 64) * 1024 + ac * 8);
        cp16(sm + PMAT + aso,          Pl + (size_t)ar * 1024 + ac * 8);
        cp16(sm + PMAT + aso + 5120,   Pl + (size_t)(ar + 64) * 1024 + ac * 8);
        cp16(sm + 2*PMAT + vso,        Vh + (size_t)vr * 1024 + vc * 8);
        cp16(sm + 2*PMAT + VMAT + vso, Vl + (size_t)vr * 1024 + vc * 8);
        cpcommit();
    }

#pragma unroll 1
    for (int kt = 0; kt < 32; kt++) {
        if (kt + 1 < 32) {
            const u32 nb = sm + ((kt + 1) & 1) * PVBUF;
            const int k0 = (kt + 1) * 32;
            cp16(nb + aso,                 Ph + (size_t)ar * 1024 + k0 + ac * 8);
            cp16(nb + aso + 5120,          Ph + (size_t)(ar + 64) * 1024 + k0 + ac * 8);
            cp16(nb + PMAT + aso,          Pl + (size_t)ar * 1024 + k0 + ac * 8);
            cp16(nb + PMAT + aso + 5120,   Pl + (size_t)(ar + 64) * 1024 + k0 + ac * 8);
            cp16(nb + 2*PMAT + vso,        Vh + (size_t)(k0 + vr) * 1024 + vc * 8);
            cp16(nb + 2*PMAT + VMAT + vso, Vl + (size_t)(k0 + vr) * 1024 + vc * 8);
            cpcommit();
            cpwait<1>();
        } else {
            cpwait<0>();
        }
        __syncthreads();
        const u32 base = sm + (kt & 1) * PVBUF;
#pragma unroll
        for (int ks = 0; ks < 2; ks++) {
            u32 ah[2][4], al[2][4], bhv[2][4], blv[2][4];
            const u32 aoff = base + (wm * 32 + lr) * 80 + ks * 32 + lc * 16;
#pragma unroll
            for (int mf = 0; mf < 2; mf++) {
                ldm4(ah[mf], aoff + mf * 1280);
                ldm4(al[mf], aoff + mf * 1280 + PMAT);
            }
            const u32 boff = base + 2 * PMAT + (ks * 16 + lr) * 144 + (wn * 32) * 2 + lc * 16;
#pragma unroll
            for (int g = 0; g < 2; g++) {
                ldm4t(bhv[g], boff + g * 32);
                ldm4t(blv[g], boff + g * 32 + VMAT);
            }
#pragma unroll
            for (int mf = 0; mf < 2; mf++)
#pragma unroll
                for (int nf = 0; nf < 4; nf++) {
                    const int g = nf >> 1, hf = nf & 1;
                    const u32 b0h = bhv[g][2 * hf], b1h = bhv[g][2 * hf + 1];
                    mma_bf(c[mf][nf], ah[mf], b0h, b1h);
                    mma_bf(c[mf][nf], al[mf], b0h, b1h);
                    mma_bf(c[mf][nf], ah[mf], blv[g][2 * hf], blv[g][2 * hf + 1]);
                }
        }
        __syncthreads();
    }

    // epilogue: write AO split
    bf16* AOh = g_AOh[o];
    bf16* AOl = g_AOl[o];
    const int rbase = wm * 32 + (lane >> 2);
    const int cbase = wn * 32 + 2 * (lane & 3);
#pragma unroll
    for (int mf = 0; mf < 2; mf++)
#pragma unroll
        for (int nf = 0; nf < 4; nf++) {
            const int row = rbase + mf * 16;
            const int col = cbase + nf * 8;
            const size_t g0 = (size_t)((b << 10) + i0 + row) * 1024 + (h << 6) + col;
            const size_t g1 = (size_t)((b << 10) + i0 + row + 8) * 1024 + (h << 6) + col;
            wsplit2(AOh, AOl, g0, c[mf][nf][0], c[mf][nf][1]);
            wsplit2(AOh, AOl, g1, c[mf][nf][2], c[mf][nf][3]);
        }
}

// ============================================================
// split_f32: hi/lo bf16 split of strided fp32 matrix (8192 x 1024)
// ============================================================
__global__ __launch_bounds__(256) void split_f32(
    const float* __restrict__ src, int stride,
    bf16* __restrict__ hi, bf16* __restrict__ lo)
{
    size_t idx = ((size_t)blockIdx.x * 256 + threadIdx.x) * 4;
    int row = (int)(idx >> 10), col = (int)(idx & 1023);
    float4 v = *(const float4*)(src + (size_t)row * stride + col);
    bf16 h0 = __float2bfloat16(v.x); bf16 l0 = __float2bfloat16(v.x - __bfloat162float(h0));
    bf16 h1 = __float2bfloat16(v.y); bf16 l1 = __float2bfloat16(v.y - __bfloat162float(h1));
    bf16 h2 = __float2bfloat16(v.z); bf16 l2 = __float2bfloat16(v.z - __bfloat162float(h2));
    bf16 h3 = __float2bfloat16(v.w); bf16 l3 = __float2bfloat16(v.w - __bfloat162float(h3));
    __nv_bfloat162 a; a.x = h0; a.y = h1;
    __nv_bfloat162 bb; bb.x = h2; bb.y = h3;
    __nv_bfloat162 cc; cc.x = l0; cc.y = l1;
    __nv_bfloat162 d; d.x = l2; d.y = l3;
    ((__nv_bfloat162*)(hi + idx))[0] = a;
    ((__nv_bfloat162*)(hi + idx))[1] = bb;
    ((__nv_bfloat162*)(lo + idx))[0] = cc;
    ((__nv_bfloat162*)(lo + idx))[1] = d;
}

// ============================================================
// transpose_split: Wt[n][k] = split(W[k][n]), 1024x1024
// ============================================================
__global__ __launch_bounds__(256) void transpose_split(
    const float* __restrict__ W, bf16* __restrict__ Th, bf16* __restrict__ Tl)
{
    __shared__ float t[32][33];
    int n0 = blockIdx.x << 5, k0 = blockIdx.y << 5;
    int tx = threadIdx.x, ty = threadIdx.y;
    for (int r = ty; r < 32; r += 8)
        t[r][tx] = W[(size_t)(k0 + r) * 1024 + n0 + tx];
    __syncthreads();
    for (int r = ty; r < 32; r += 8) {
        float v = t[tx][r];
        bf16 h = __float2bfloat16(v);
        bf16 l = __float2bfloat16(v - __bfloat162float(h));
        Th[(size_t)(n0 + r) * 1024 + k0 + tx] = h;
        Tl[(size_t)(n0 + r) * 1024 + k0 + tx] = l;
    }
}

// ============================================================
// Launch
// ============================================================
extern "C" void kernel_launch(void* const* d_in, const int* in_sizes, int n_in,
                              void* d_out, int out_size)
{
    const float* x  = (const float*)d_in[0];
    const float* Wq = (const float*)d_in[1];
    const float* bq = (const float*)d_in[2];
    const float* Wk = (const float*)d_in[3];
    const float* bk = (const float*)d_in[4];
    const float* Wv = (const float*)d_in[5];
    const float* bv = (const float*)d_in[6];
    const float* Wo = (const float*)d_in[7];
    const float* bo = (const float*)d_in[8];
    float* out = (float*)d_out;

    static bool attr_set = false;
    if (!attr_set) {
        cudaFuncSetAttribute(hgemm_nk, cudaFuncAttributeMaxDynamicSharedMemorySize, GEMM_SMEM);
        cudaFuncSetAttribute(hscores, cudaFuncAttributeMaxDynamicSharedMemorySize, GEMM_SMEM);
        cudaFuncSetAttribute(hpv, cudaFuncAttributeMaxDynamicSharedMemorySize, PV_SMEM);
        attr_set = true;
    }

    bf16 *Ah, *Al, *Qh, *Ql, *Kh, *Kl, *Vh, *Vl, *AOh, *AOl, *Wth, *Wtl;
    cudaGetSymbolAddress((void**)&Ah, g_Ah);   cudaGetSymbolAddress((void**)&Al, g_Al);
    cudaGetSymbolAddress((void**)&Qh, g_Qh);   cudaGetSymbolAddress((void**)&Ql, g_Ql);
    cudaGetSymbolAddress((void**)&Kh, g_Kh);   cudaGetSymbolAddress((void**)&Kl, g_Kl);
    cudaGetSymbolAddress((void**)&Vh, g_Vh);   cudaGetSymbolAddress((void**)&Vl, g_Vl);
    cudaGetSymbolAddress((void**)&AOh, g_AOh); cudaGetSymbolAddress((void**)&AOl, g_AOl);
    cudaGetSymbolAddress((void**)&Wth, g_Wth); cudaGetSymbolAddress((void**)&Wtl, g_Wtl);

    // 0) input splits + weight transpose-splits
    for (int s = 0; s < 3; s++)
        split_f32<<<8192, 256>>>(x + s * 1024, 3072, Ah + s * NN, Al + s * NN);
    const float* Wp[4] = { Wq, Wk, Wv, Wo };
    for (int w = 0; w < 4; w++)
        transpose_split<<<dim3(32, 32), dim3(32, 8)>>>(Wp[w], Wth + w * NW, Wtl + w * NW);

    // 1) projections -> bf16 splits
    dim3 gP(8, 64);
    for (int s = 0; s < 3; s++) {
        hgemm_nk<<<gP, 256, GEMM_SMEM>>>(Ah + s * NN, Al + s * NN,
                                         Wth + 0 * NW, Wtl + 0 * NW, bq,
                                         nullptr, 0, Qh + s * NN, Ql + s * NN);
        hgemm_nk<<<gP, 256, GEMM_SMEM>>>(Ah + s * NN, Al + s * NN,
                                         Wth + 1 * NW, Wtl + 1 * NW, bk,
                                         nullptr, 0, Kh + s * NN, Kl + s * NN);
        hgemm_nk<<<gP, 256, GEMM_SMEM>>>(Ah + s * NN, Al + s * NN,
                                         Wth + 2 * NW, Wtl + 2 * NW, bv,
                                         nullptr, 0, Vh + s * NN, Vl + s * NN);
    }

    // 2) scores (computed once, consumed twice)
    hscores<<<dim3(8, 8, 384), 256, GEMM_SMEM>>>();

    // 3) dual softmax -> P bf16 split
    softmax_dual<<<dim3(128, 128, 3), 256>>>();

    // 4) P @ V -> AO bf16 split
    hpv<<<dim3(8, 128, 3), 256, PV_SMEM>>>();

    // 5) output projection into (B, L, 3, D)
    for (int s = 0; s < 3; s++)
        hgemm_nk<<<gP, 256, GEMM_SMEM>>>(AOh + s * NN, AOl + s * NN,
                                         Wth + 3 * NW, Wtl + 3 * NW, bo,
                                         out + s * 1024, 3072, nullptr, nullptr);
}

// round 5
// speedup vs baseline: 3.9233x; 1.7607x over previous
#include <cuda_runtime.h>
#include <cuda_bf16.h>
#include <cstdint>

typedef __nv_bfloat16 bf16;
typedef unsigned int u32;

#define NN 8388608ULL      // 8192*1024
#define NW 1048576ULL      // 1024*1024

// ---------------- global scratch ----------------
__device__ bf16 g_Ah[3][NN], g_Al[3][NN];        // x split
__device__ bf16 g_Qh[3][NN], g_Ql[3][NN];
__device__ bf16 g_Kh[3][NN], g_Kl[3][NN];
__device__ bf16 g_Vh[3][NN], g_Vl[3][NN];
__device__ bf16 g_AOh[3][NN], g_AOl[3][NN];      // attention out split
__device__ float g_S[3][128][NW];                // scaled scores fp32
__device__ bf16 g_Wth[4][NW], g_Wtl[4][NW];      // W^T splits [q,k,v,o] (q|k|v rows contiguous)

// ---------------- PTX helpers ----------------
__device__ __forceinline__ u32 smem_u32(const void* p) {
    u32 a;
    asm("{ .reg .u64 t; cvta.to.shared.u64 t, %1; cvt.u32.u64 %0, t; }" : "=r"(a) : "l"(p));
    return a;
}
__device__ __forceinline__ void cp16(u32 d, const void* s) {
    asm volatile("cp.async.cg.shared.global [%0], [%1], 16;" :: "r"(d), "l"(s));
}
__device__ __forceinline__ void cpcommit() { asm volatile("cp.async.commit_group;"); }
template<int N> __device__ __forceinline__ void cpwait() {
    asm volatile("cp.async.wait_group %0;" :: "n"(N));
}
__device__ __forceinline__ void ldm4(u32* r, u32 a) {
    asm volatile("ldmatrix.sync.aligned.m8n8.x4.shared.b16 {%0,%1,%2,%3}, [%4];"
                 : "=r"(r[0]), "=r"(r[1]), "=r"(r[2]), "=r"(r[3]) : "r"(a));
}
__device__ __forceinline__ void ldm4t(u32* r, u32 a) {
    asm volatile("ldmatrix.sync.aligned.m8n8.x4.trans.shared.b16 {%0,%1,%2,%3}, [%4];"
                 : "=r"(r[0]), "=r"(r[1]), "=r"(r[2]), "=r"(r[3]) : "r"(a));
}
__device__ __forceinline__ void mma_bf(float* c, const u32* a, u32 b0, u32 b1) {
    asm volatile(
        "mma.sync.aligned.m16n8k16.row.col.f32.bf16.bf16.f32 "
        "{%0,%1,%2,%3}, {%4,%5,%6,%7}, {%8,%9}, {%0,%1,%2,%3};"
        : "+f"(c[0]), "+f"(c[1]), "+f"(c[2]), "+f"(c[3])
        : "r"(a[0]), "r"(a[1]), "r"(a[2]), "r"(a[3]), "r"(b0), "r"(b1));
}
__device__ __forceinline__ void wsplit2(bf16* H, bf16* L, size_t off, float v0, float v1) {
    bf16 h0 = __float2bfloat16(v0); bf16 l0 = __float2bfloat16(v0 - __bfloat162float(h0));
    bf16 h1 = __float2bfloat16(v1); bf16 l1 = __float2bfloat16(v1 - __bfloat162float(h1));
    __nv_bfloat162 hh; hh.x = h0; hh.y = h1;
    __nv_bfloat162 ll; ll.x = l0; ll.y = l1;
    *(__nv_bfloat162*)(H + off) = hh;
    *(__nv_bfloat162*)(L + off) = ll;
}
__device__ __forceinline__ u32 packbf(float a, float b) {
    __nv_bfloat162 t; t.x = __float2bfloat16(a); t.y = __float2bfloat16(b);
    return *(u32*)&t;
}

// ============================================================
// Shared GEMM core: 128x128 CTA tile, BK=32, 256 thr, 8 warps (2m x 4n),
// warp tile 64x32, bf16 hi/lo 3-term split, cp.async double buffer.
// smem row stride 80B -> conflict-free ldmatrix.
// ============================================================
#define GMAT 10240        // 128*80
#define GBUF 40960        // 4 matrices
#define GEMM_SMEM 81920   // 2 buffers

__device__ __forceinline__ void stage_g(u32 sm,
    const bf16* __restrict__ Ah, const bf16* __restrict__ Al, int lda,
    const bf16* __restrict__ Bh, const bf16* __restrict__ Bl, int ldb,
    int k0, int tid)
{
    const int r = tid >> 2, cc = tid & 3;
    const u32 so = r * 80 + cc * 16;
    const int co = k0 + cc * 8;
    cp16(sm + so,                 Ah + (size_t)r * lda + co);
    cp16(sm + so + 5120,          Ah + (size_t)(r + 64) * lda + co);
    cp16(sm + GMAT + so,          Al + (size_t)r * lda + co);
    cp16(sm + GMAT + so + 5120,   Al + (size_t)(r + 64) * lda + co);
    cp16(sm + 2*GMAT + so,        Bh + (size_t)r * ldb + co);
    cp16(sm + 2*GMAT + so + 5120, Bh + (size_t)(r + 64) * ldb + co);
    cp16(sm + 3*GMAT + so,        Bl + (size_t)r * ldb + co);
    cp16(sm + 3*GMAT + so + 5120, Bl + (size_t)(r + 64) * ldb + co);
}

__device__ __forceinline__ void gemm_core(u32 sm,
    const bf16* __restrict__ Ah, const bf16* __restrict__ Al, int lda,
    const bf16* __restrict__ Bh, const bf16* __restrict__ Bl, int ldb,
    int nk, float c[4][4][4])
{
    const int tid = threadIdx.x, wid = tid >> 5, lane = tid & 31;
    const int wm = wid >> 2, wn = wid & 3;
    const int lr = lane & 15, lc = lane >> 4;

    stage_g(sm, Ah, Al, lda, Bh, Bl, ldb, 0, tid);
    cpcommit();

#pragma unroll 1
    for (int kt = 0; kt < nk; kt++) {
        if (kt + 1 < nk) {
            stage_g(sm + ((kt + 1) & 1) * GBUF, Ah, Al, lda, Bh, Bl, ldb, (kt + 1) * 32, tid);
            cpcommit();
            cpwait<1>();
        } else {
            cpwait<0>();
        }
        __syncthreads();
        const u32 base = sm + (kt & 1) * GBUF;
#pragma unroll
        for (int ks = 0; ks < 2; ks++) {
            u32 ah[4][4], al[4][4], bh[2][4], bl[2][4];
            const u32 aoff = base + (wm * 64 + lr) * 80 + ks * 32 + lc * 16;
#pragma unroll
            for (int mf = 0; mf < 4; mf++) {
                ldm4(ah[mf], aoff + mf * 1280);
                ldm4(al[mf], aoff + mf * 1280 + GMAT);
            }
            const u32 boff = base + 2 * GMAT + (wn * 32 + lr) * 80 + ks * 32 + lc * 16;
#pragma unroll
            for (int g = 0; g < 2; g++) {
                ldm4(bh[g], boff + g * 1280);
                ldm4(bl[g], boff + g * 1280 + GMAT);
            }
#pragma unroll
            for (int mf = 0; mf < 4; mf++)
#pragma unroll
                for (int nf = 0; nf < 4; nf++) {
                    const int g = nf >> 1, od = nf & 1;
                    mma_bf(c[mf][nf], ah[mf], bh[g][od], bh[g][od + 2]);
                    mma_bf(c[mf][nf], al[mf], bh[g][od], bh[g][od + 2]);
                    mma_bf(c[mf][nf], ah[mf], bl[g][od], bl[g][od + 2]);
                }
        }
        __syncthreads();
    }
}

// ============================================================
// hproj: batched QKV projections. grid (24 n-tiles over q|k|v, 64 m, 3 streams)
// writes bf16 splits directly into g_Q/g_K/g_V.
// ============================================================
__global__ __launch_bounds__(256) void hproj(
    const bf16* __restrict__ AhB, const bf16* __restrict__ AlB,
    const float* __restrict__ bq, const float* __restrict__ bk,
    const float* __restrict__ bv)
{
    extern __shared__ __align__(16) char smraw[];
    const u32 sm = smem_u32(smraw);
    const int s = blockIdx.z;
    const int bm = blockIdx.y << 7;
    const int bnG = blockIdx.x << 7;            // 0..3071
    const int p = bnG >> 10, bnL = bnG & 1023;

    const float* bias = (p == 0) ? bq : (p == 1) ? bk : bv;
    bf16* oh = (p == 0) ? g_Qh[s] : (p == 1) ? g_Kh[s] : g_Vh[s];
    bf16* ol = (p == 0) ? g_Ql[s] : (p == 1) ? g_Kl[s] : g_Vl[s];

    float c[4][4][4];
#pragma unroll
    for (int i = 0; i < 4; i++)
#pragma unroll
        for (int j = 0; j < 4; j++)
#pragma unroll
            for (int k = 0; k < 4; k++) c[i][j][k] = 0.f;

    gemm_core(sm, AhB + s * NN + (size_t)bm * 1024, AlB + s * NN + (size_t)bm * 1024, 1024,
              &g_Wth[0][0] + (size_t)bnG * 1024, &g_Wtl[0][0] + (size_t)bnG * 1024, 1024, 32, c);

    const int wid = threadIdx.x >> 5, lane = threadIdx.x & 31;
    const int wm = wid >> 2, wn = wid & 3;
    const int rbase = bm + wm * 64 + (lane >> 2);
    const int cbase = bnL + wn * 32 + 2 * (lane & 3);
#pragma unroll
    for (int mf = 0; mf < 4; mf++)
#pragma unroll
        for (int nf = 0; nf < 4; nf++) {
            const int col = cbase + nf * 8;
            const float b0 = bias[col], b1 = bias[col + 1];
            const int row = rbase + mf * 16;
            wsplit2(oh, ol, (size_t)row * 1024 + col, c[mf][nf][0] + b0, c[mf][nf][1] + b1);
            wsplit2(oh, ol, (size_t)(row + 8) * 1024 + col, c[mf][nf][2] + b0, c[mf][nf][3] + b1);
        }
}

// ============================================================
// hout: batched output projection. grid (8, 64, 3). fp32 out (B,L,3,D).
// ============================================================
__global__ __launch_bounds__(256) void hout(
    const bf16* __restrict__ AOhB, const bf16* __restrict__ AOlB,
    const float* __restrict__ bo, float* __restrict__ out)
{
    extern __shared__ __align__(16) char smraw[];
    const u32 sm = smem_u32(smraw);
    const int s = blockIdx.z;
    const int bm = blockIdx.y << 7, bn = blockIdx.x << 7;

    float c[4][4][4];
#pragma unroll
    for (int i = 0; i < 4; i++)
#pragma unroll
        for (int j = 0; j < 4; j++)
#pragma unroll
            for (int k = 0; k < 4; k++) c[i][j][k] = 0.f;

    gemm_core(sm, AOhB + s * NN + (size_t)bm * 1024, AOlB + s * NN + (size_t)bm * 1024, 1024,
              &g_Wth[3][0] + (size_t)bn * 1024, &g_Wtl[3][0] + (size_t)bn * 1024, 1024, 32, c);

    float* outF = out + s * 1024;
    const int wid = threadIdx.x >> 5, lane = threadIdx.x & 31;
    const int wm = wid >> 2, wn = wid & 3;
    const int rbase = bm + wm * 64 + (lane >> 2);
    const int cbase = bn + wn * 32 + 2 * (lane & 3);
#pragma unroll
    for (int mf = 0; mf < 4; mf++)
#pragma unroll
        for (int nf = 0; nf < 4; nf++) {
            const int col = cbase + nf * 8;
            const float b0 = bo[col], b1 = bo[col + 1];
            const int row = rbase + mf * 16;
            *(float2*)(outF + (size_t)row * 3072 + col) =
                make_float2(c[mf][nf][0] + b0, c[mf][nf][1] + b1);
            *(float2*)(outF + (size_t)(row + 8) * 3072 + col) =
                make_float2(c[mf][nf][2] + b0, c[mf][nf][3] + b1);
        }
}

// ============================================================
// hscores: S_s[bh] = (q.k^T)*0.0625, K=64 (nk=2). grid (8 j, 8 i, 384)
// ============================================================
__global__ __launch_bounds__(256) void hscores()
{
    extern __shared__ __align__(16) char smraw[];
    const u32 sm = smem_u32(smraw);
    const int z = blockIdx.z;
    const int s = z >> 7, bh = z & 127, b = bh >> 4, h = bh & 15;
    const int i0 = blockIdx.y << 7, j0 = blockIdx.x << 7;

    const size_t qo = (size_t)((b << 10) + i0) * 1024 + (h << 6);
    const size_t ko = (size_t)((b << 10) + j0) * 1024 + (h << 6);

    float c[4][4][4];
#pragma unroll
    for (int i = 0; i < 4; i++)
#pragma unroll
        for (int j = 0; j < 4; j++)
#pragma unroll
            for (int k = 0; k < 4; k++) c[i][j][k] = 0.f;

    gemm_core(sm, g_Qh[s] + qo, g_Ql[s] + qo, 1024,
              g_Kh[s] + ko, g_Kl[s] + ko, 1024, 2, c);

    const int wid = threadIdx.x >> 5, lane = threadIdx.x & 31;
    const int wm = wid >> 2, wn = wid & 3;
    const int rbase = i0 + wm * 64 + (lane >> 2);
    const int cbase = j0 + wn * 32 + 2 * (lane & 3);
    float* Sg = g_S[s][bh];
#pragma unroll
    for (int mf = 0; mf < 4; mf++)
#pragma unroll
        for (int nf = 0; nf < 4; nf++) {
            const int row = rbase + mf * 16, col = cbase + nf * 8;
            *(float2*)(Sg + (size_t)row * 1024 + col) =
                make_float2(c[mf][nf][0] * 0.0625f, c[mf][nf][1] * 0.0625f);
            *(float2*)(Sg + (size_t)(row + 8) * 1024 + col) =
                make_float2(c[mf][nf][2] * 0.0625f, c[mf][nf][3] * 0.0625f);
        }
}

// ============================================================
// hspv: fused softmax(S_a+S_b) @ V, NO max subtraction (logits bounded):
//   p = exp(sa+sb) (unnormalized, bf16 hi/lo), O = (P @ V) / rowsum(P).
// CTA: 128 q-rows x 64 dims, loop over 16 k-tiles of 64.
// smem: P tile (hi/lo, stride 144), V double-buffered (hi/lo), rowsum L.
// grid (8 q-tiles, 128 bh, 3 o), 256 thr, 8 warps (4m x 2n), warp 32x32.
// ============================================================
#define SPV_PL 18432
#define SPV_V  36864
#define SPV_SL 73728
#define SPV_SMEM 74752

__global__ __launch_bounds__(256, 2) void hspv()
{
    extern __shared__ __align__(16) char smraw[];
    const u32 sm = smem_u32(smraw);
    float* sL = (float*)(smraw + SPV_SL);

    const int tid = threadIdx.x, wid = tid >> 5, lane = tid & 31;
    const int o = blockIdx.z, bh = blockIdx.y;
    const int b = bh >> 4, h = bh & 15;
    const int i0 = blockIdx.x << 7;
    const int sa = (o == 0) ? 1 : 0;
    const int sb = (o == 2) ? 1 : 2;

    const float* Sa = g_S[sa][bh] + (size_t)i0 * 1024;
    const float* Sb = g_S[sb][bh] + (size_t)i0 * 1024;
    const bf16* Vh = g_Vh[o] + ((size_t)(b << 10)) * 1024 + (h << 6);
    const bf16* Vl = g_Vl[o] + ((size_t)(b << 10)) * 1024 + (h << 6);

    // V staging: 64 rows x 64 d bf16, stride 144, hi at +0 / lo at +9216
    const int sv_r0 = tid >> 3, sv_c = tid & 7;       // it=0
    const int sv_r1 = (256 + tid) >> 3;               // it=1

    // prologue: V tile 0 into buf 0
    {
        const u32 d0 = sm + SPV_V;
        cp16(d0 + sv_r0 * 144 + sv_c * 16,        Vh + (size_t)sv_r0 * 1024 + sv_c * 8);
        cp16(d0 + 9216 + sv_r0 * 144 + sv_c * 16, Vl + (size_t)sv_r0 * 1024 + sv_c * 8);
        cp16(d0 + sv_r1 * 144 + sv_c * 16,        Vh + (size_t)sv_r1 * 1024 + sv_c * 8);
        cp16(d0 + 9216 + sv_r1 * 144 + sv_c * 16, Vl + (size_t)sv_r1 * 1024 + sv_c * 8);
        cpcommit();
    }

    // p-compute mapping: rows ps*16 + w2, cols col4..col4+3 of the 64-wide tile
    const int w2 = wid * 2 + (lane >> 4);
    const int col4 = (lane & 15) * 4;

    float Lsum[8];
#pragma unroll
    for (int i = 0; i < 8; i++) Lsum[i] = 0.f;

    float c[2][4][4];
#pragma unroll
    for (int i = 0; i < 2; i++)
#pragma unroll
        for (int j = 0; j < 4; j++)
#pragma unroll
            for (int k = 0; k < 4; k++) c[i][j][k] = 0.f;

    const int wm = wid & 3, wn = wid >> 2;
    const int lr = lane & 15, lc = lane >> 4;

#pragma unroll 1
    for (int kt = 0; kt < 16; kt++) {
        // ---- compute p tile (128 x 64) ----
        const int kc = kt * 64 + col4;
#pragma unroll
        for (int ps = 0; ps < 8; ps++) {
            const int row = ps * 16 + w2;
            const float4 va = *(const float4*)(Sa + (size_t)row * 1024 + kc);
            const float4 vb = *(const float4*)(Sb + (size_t)row * 1024 + kc);
            const float p0 = __expf(va.x + vb.x);
            const float p1 = __expf(va.y + vb.y);
            const float p2 = __expf(va.z + vb.z);
            const float p3 = __expf(va.w + vb.w);
            Lsum[ps] += (p0 + p1) + (p2 + p3);
            bf16 h0 = __float2bfloat16(p0); float l0 = p0 - __bfloat162float(h0);
            bf16 h1 = __float2bfloat16(p1); float l1 = p1 - __bfloat162float(h1);
            bf16 h2 = __float2bfloat16(p2); float l2 = p2 - __bfloat162float(h2);
            bf16 h3 = __float2bfloat16(p3); float l3 = p3 - __bfloat162float(h3);
            __nv_bfloat162 t01; t01.x = h0; t01.y = h1;
            __nv_bfloat162 t23; t23.x = h2; t23.y = h3;
            const u32 hA = *(u32*)&t01, hB = *(u32*)&t23;
            const u32 lA = packbf(l0, l1), lB = packbf(l2, l3);
            const u32 ad = sm + row * 144 + col4 * 2;
            asm volatile("st.shared.v2.b32 [%0], {%1,%2};" :: "r"(ad), "r"(hA), "r"(hB) : "memory");
            asm volatile("st.shared.v2.b32 [%0], {%1,%2};" :: "r"(ad + SPV_PL), "r"(lA), "r"(lB) : "memory");
        }
        // ---- stage next V tile ----
        if (kt + 1 < 16) {
            const u32 nb = sm + SPV_V + ((kt + 1) & 1) * 18432;
            const int k0 = (kt + 1) * 64;
            cp16(nb + sv_r0 * 144 + sv_c * 16,        Vh + (size_t)(k0 + sv_r0) * 1024 + sv_c * 8);
            cp16(nb + 9216 + sv_r0 * 144 + sv_c * 16, Vl + (size_t)(k0 + sv_r0) * 1024 + sv_c * 8);
            cp16(nb + sv_r1 * 144 + sv_c * 16,        Vh + (size_t)(k0 + sv_r1) * 1024 + sv_c * 8);
            cp16(nb + 9216 + sv_r1 * 144 + sv_c * 16, Vl + (size_t)(k0 + sv_r1) * 1024 + sv_c * 8);
            cpcommit();
            cpwait<1>();
        } else {
            cpwait<0>();
        }
        __syncthreads();
        // ---- MMA: P(128x64) @ V(64x64) ----
        const u32 vb2 = sm + SPV_V + (kt & 1) * 18432;
#pragma unroll
        for (int ks = 0; ks < 4; ks++) {
            u32 ah[2][4], al[2][4], bhv[2][4], blv[2][4];
            const u32 aoff = sm + (wm * 32 + lr) * 144 + ks * 32 + lc * 16;
#pragma unroll
            for (int mf = 0; mf < 2; mf++) {
                ldm4(ah[mf], aoff + mf * 2304);
                ldm4(al[mf], aoff + mf * 2304 + SPV_PL);
            }
            const u32 boff = vb2 + (ks * 16 + lr) * 144 + wn * 64 + lc * 16;
#pragma unroll
            for (int g = 0; g < 2; g++) {
                ldm4t(bhv[g], boff + g * 32);
                ldm4t(blv[g], boff + g * 32 + 9216);
            }
#pragma unroll
            for (int mf = 0; mf < 2; mf++)
#pragma unroll
                for (int nf = 0; nf < 4; nf++) {
                    const int g = nf >> 1, hf = nf & 1;
                    mma_bf(c[mf][nf], ah[mf], bhv[g][2 * hf], bhv[g][2 * hf + 1]);
                    mma_bf(c[mf][nf], al[mf], bhv[g][2 * hf], bhv[g][2 * hf + 1]);
                    mma_bf(c[mf][nf], ah[mf], blv[g][2 * hf], blv[g][2 * hf + 1]);
                }
        }
        __syncthreads();
    }

    // ---- row-sum reduction: 16 lanes per row ----
#pragma unroll
    for (int ps = 0; ps < 8; ps++) {
        float v = Lsum[ps];
        v += __shfl_xor_sync(0xffffffffu, v, 1);
        v += __shfl_xor_sync(0xffffffffu, v, 2);
        v += __shfl_xor_sync(0xffffffffu, v, 4);
        v += __shfl_xor_sync(0xffffffffu, v, 8);
        if ((lane & 15) == 0) sL[ps * 16 + w2] = v;
    }
    __syncthreads();

    // ---- epilogue: normalize + write AO split ----
    bf16* AOh = g_AOh[o];
    bf16* AOl = g_AOl[o];
    const int rbase = wm * 32 + (lane >> 2);
    const int cbase = wn * 32 + 2 * (lane & 3);
#pragma unroll
    for (int mf = 0; mf < 2; mf++) {
        const int r0 = rbase + mf * 16;
        const float inv0 = 1.0f / sL[r0];
        const float inv1 = 1.0f / sL[r0 + 8];
#pragma unroll
        for (int nf = 0; nf < 4; nf++) {
            const int col = cbase + nf * 8;
            const size_t g0 = (size_t)((b << 10) + i0 + r0) * 1024 + (h << 6) + col;
            const size_t g1 = (size_t)((b << 10) + i0 + r0 + 8) * 1024 + (h << 6) + col;
            wsplit2(AOh, AOl, g0, c[mf][nf][0] * inv0, c[mf][nf][1] * inv0);
            wsplit2(AOh, AOl, g1, c[mf][nf][2] * inv1, c[mf][nf][3] * inv1);
        }
    }
}

// ============================================================
// split_f32 / transpose_split (unchanged)
// ============================================================
__global__ __launch_bounds__(256) void split_f32(
    const float* __restrict__ src, int stride,
    bf16* __restrict__ hi, bf16* __restrict__ lo)
{
    size_t idx = ((size_t)blockIdx.x * 256 + threadIdx.x) * 4;
    int row = (int)(idx >> 10), col = (int)(idx & 1023);
    float4 v = *(const float4*)(src + (size_t)row * stride + col);
    bf16 h0 = __float2bfloat16(v.x); bf16 l0 = __float2bfloat16(v.x - __bfloat162float(h0));
    bf16 h1 = __float2bfloat16(v.y); bf16 l1 = __float2bfloat16(v.y - __bfloat162float(h1));
    bf16 h2 = __float2bfloat16(v.z); bf16 l2 = __float2bfloat16(v.z - __bfloat162float(h2));
    bf16 h3 = __float2bfloat16(v.w); bf16 l3 = __float2bfloat16(v.w - __bfloat162float(h3));
    __nv_bfloat162 a; a.x = h0; a.y = h1;
    __nv_bfloat162 bb; bb.x = h2; bb.y = h3;
    __nv_bfloat162 cc; cc.x = l0; cc.y = l1;
    __nv_bfloat162 d; d.x = l2; d.y = l3;
    ((__nv_bfloat162*)(hi + idx))[0] = a;
    ((__nv_bfloat162*)(hi + idx))[1] = bb;
    ((__nv_bfloat162*)(lo + idx))[0] = cc;
    ((__nv_bfloat162*)(lo + idx))[1] = d;
}

__global__ __launch_bounds__(256) void transpose_split(
    const float* __restrict__ W, bf16* __restrict__ Th, bf16* __restrict__ Tl)
{
    __shared__ float t[32][33];
    int n0 = blockIdx.x << 5, k0 = blockIdx.y << 5;
    int tx = threadIdx.x, ty = threadIdx.y;
    for (int r = ty; r < 32; r += 8)
        t[r][tx] = W[(size_t)(k0 + r) * 1024 + n0 + tx];
    __syncthreads();
    for (int r = ty; r < 32; r += 8) {
        float v = t[tx][r];
        bf16 h = __float2bfloat16(v);
        bf16 l = __float2bfloat16(v - __bfloat162float(h));
        Th[(size_t)(n0 + r) * 1024 + k0 + tx] = h;
        Tl[(size_t)(n0 + r) * 1024 + k0 + tx] = l;
    }
}

// ============================================================
// Launch
// ============================================================
extern "C" void kernel_launch(void* const* d_in, const int* in_sizes, int n_in,
                              void* d_out, int out_size)
{
    const float* x  = (const float*)d_in[0];
    const float* Wq = (const float*)d_in[1];
    const float* bq = (const float*)d_in[2];
    const float* Wk = (const float*)d_in[3];
    const float* bk = (const float*)d_in[4];
    const float* Wv = (const float*)d_in[5];
    const float* bv = (const float*)d_in[6];
    const float* Wo = (const float*)d_in[7];
    const float* bo = (const float*)d_in[8];
    float* out = (float*)d_out;

    static bool attr_set = false;
    if (!attr_set) {
        cudaFuncSetAttribute(hproj, cudaFuncAttributeMaxDynamicSharedMemorySize, GEMM_SMEM);
        cudaFuncSetAttribute(hout, cudaFuncAttributeMaxDynamicSharedMemorySize, GEMM_SMEM);
        cudaFuncSetAttribute(hscores, cudaFuncAttributeMaxDynamicSharedMemorySize, GEMM_SMEM);
        cudaFuncSetAttribute(hspv, cudaFuncAttributeMaxDynamicSharedMemorySize, SPV_SMEM);
        attr_set = true;
    }

    bf16 *Ah, *Al, *AOh, *AOl, *Wth, *Wtl;
    cudaGetSymbolAddress((void**)&Ah, g_Ah);   cudaGetSymbolAddress((void**)&Al, g_Al);
    cudaGetSymbolAddress((void**)&AOh, g_AOh); cudaGetSymbolAddress((void**)&AOl, g_AOl);
    cudaGetSymbolAddress((void**)&Wth, g_Wth); cudaGetSymbolAddress((void**)&Wtl, g_Wtl);

    // 0) input splits + weight transpose-splits (q|k|v rows land contiguous in g_Wth[0..2])
    for (int s = 0; s < 3; s++)
        split_f32<<<8192, 256>>>(x + s * 1024, 3072, Ah + s * NN, Al + s * NN);
    const float* Wp[4] = { Wq, Wk, Wv, Wo };
    for (int w = 0; w < 4; w++)
        transpose_split<<<dim3(32, 32), dim3(32, 8)>>>(Wp[w], Wth + w * NW, Wtl + w * NW);

    // 1) batched QKV projections (one launch)
    hproj<<<dim3(24, 64, 3), 256, GEMM_SMEM>>>(Ah, Al, bq, bk, bv);

    // 2) scores (computed once, consumed twice)
    hscores<<<dim3(8, 8, 384), 256, GEMM_SMEM>>>();

    // 3+4) fused dual-softmax (no max subtraction) + PV
    hspv<<<dim3(8, 128, 3), 256, SPV_SMEM>>>();

    // 5) batched output projection
    hout<<<dim3(8, 64, 3), 256, GEMM_SMEM>>>(AOh, AOl, bo, out);
}

// round 6
// speedup vs baseline: 4.1773x; 1.0648x over previous
#include <cuda_runtime.h>
#include <cuda_bf16.h>
#include <cstdint>

typedef __nv_bfloat16 bf16;
typedef unsigned int u32;

#define NN 8388608ULL      // 8192*1024
#define NW 1048576ULL      // 1024*1024

// ---------------- global scratch ----------------
__device__ bf16 g_Ah[3][NN], g_Al[3][NN];        // x split
__device__ bf16 g_Qh[3][NN], g_Ql[3][NN];
__device__ bf16 g_Kh[3][NN], g_Kl[3][NN];
__device__ bf16 g_Vh[3][NN], g_Vl[3][NN];
__device__ bf16 g_AOh[3][NN], g_AOl[3][NN];      // attention out split
__device__ bf16 g_Wth[4][NW], g_Wtl[4][NW];      // W^T splits [q,k,v,o] contiguous

// ---------------- PTX helpers ----------------
__device__ __forceinline__ u32 smem_u32(const void* p) {
    u32 a;
    asm("{ .reg .u64 t; cvta.to.shared.u64 t, %1; cvt.u32.u64 %0, t; }" : "=r"(a) : "l"(p));
    return a;
}
__device__ __forceinline__ void cp16(u32 d, const void* s) {
    asm volatile("cp.async.cg.shared.global [%0], [%1], 16;" :: "r"(d), "l"(s));
}
__device__ __forceinline__ void cpcommit() { asm volatile("cp.async.commit_group;"); }
template<int N> __device__ __forceinline__ void cpwait() {
    asm volatile("cp.async.wait_group %0;" :: "n"(N));
}
__device__ __forceinline__ void ldm4(u32* r, u32 a) {
    asm volatile("ldmatrix.sync.aligned.m8n8.x4.shared.b16 {%0,%1,%2,%3}, [%4];"
                 : "=r"(r[0]), "=r"(r[1]), "=r"(r[2]), "=r"(r[3]) : "r"(a));
}
__device__ __forceinline__ void ldm4t(u32* r, u32 a) {
    asm volatile("ldmatrix.sync.aligned.m8n8.x4.trans.shared.b16 {%0,%1,%2,%3}, [%4];"
                 : "=r"(r[0]), "=r"(r[1]), "=r"(r[2]), "=r"(r[3]) : "r"(a));
}
__device__ __forceinline__ void mma_bf(float* c, const u32* a, u32 b0, u32 b1) {
    asm volatile(
        "mma.sync.aligned.m16n8k16.row.col.f32.bf16.bf16.f32 "
        "{%0,%1,%2,%3}, {%4,%5,%6,%7}, {%8,%9}, {%0,%1,%2,%3};"
        : "+f"(c[0]), "+f"(c[1]), "+f"(c[2]), "+f"(c[3])
        : "r"(a[0]), "r"(a[1]), "r"(a[2]), "r"(a[3]), "r"(b0), "r"(b1));
}
__device__ __forceinline__ void wsplit2(bf16* H, bf16* L, size_t off, float v0, float v1) {
    bf16 h0 = __float2bfloat16(v0); bf16 l0 = __float2bfloat16(v0 - __bfloat162float(h0));
    bf16 h1 = __float2bfloat16(v1); bf16 l1 = __float2bfloat16(v1 - __bfloat162float(h1));
    __nv_bfloat162 hh; hh.x = h0; hh.y = h1;
    __nv_bfloat162 ll; ll.x = l0; ll.y = l1;
    *(__nv_bfloat162*)(H + off) = hh;
    *(__nv_bfloat162*)(L + off) = ll;
}
__device__ __forceinline__ u32 packbf(float a, float b) {
    __nv_bfloat162 t; t.x = __float2bfloat16(a); t.y = __float2bfloat16(b);
    return *(u32*)&t;
}
__device__ __forceinline__ void sts32(u32 a, u32 v) {
    asm volatile("st.shared.b32 [%0], %1;" :: "r"(a), "r"(v) : "memory");
}

// ============================================================
// Shared GEMM core (unchanged from R5): 128x128 tile, BK=32, 256 thr,
// 8 warps (2m x 4n), warp 64x32, 3-term split, cp.async double buffer.
// ============================================================
#define GMAT 10240
#define GBUF 40960
#define GEMM_SMEM 81920

__device__ __forceinline__ void stage_g(u32 sm,
    const bf16* __restrict__ Ah, const bf16* __restrict__ Al, int lda,
    const bf16* __restrict__ Bh, const bf16* __restrict__ Bl, int ldb,
    int k0, int tid)
{
    const int r = tid >> 2, cc = tid & 3;
    const u32 so = r * 80 + cc * 16;
    const int co = k0 + cc * 8;
    cp16(sm + so,                 Ah + (size_t)r * lda + co);
    cp16(sm + so + 5120,          Ah + (size_t)(r + 64) * lda + co);
    cp16(sm + GMAT + so,          Al + (size_t)r * lda + co);
    cp16(sm + GMAT + so + 5120,   Al + (size_t)(r + 64) * lda + co);
    cp16(sm + 2*GMAT + so,        Bh + (size_t)r * ldb + co);
    cp16(sm + 2*GMAT + so + 5120, Bh + (size_t)(r + 64) * ldb + co);
    cp16(sm + 3*GMAT + so,        Bl + (size_t)r * ldb + co);
    cp16(sm + 3*GMAT + so + 5120, Bl + (size_t)(r + 64) * ldb + co);
}

__device__ __forceinline__ void gemm_core(u32 sm,
    const bf16* __restrict__ Ah, const bf16* __restrict__ Al, int lda,
    const bf16* __restrict__ Bh, const bf16* __restrict__ Bl, int ldb,
    int nk, float c[4][4][4])
{
    const int tid = threadIdx.x, wid = tid >> 5, lane = tid & 31;
    const int wm = wid >> 2, wn = wid & 3;
    const int lr = lane & 15, lc = lane >> 4;

    stage_g(sm, Ah, Al, lda, Bh, Bl, ldb, 0, tid);
    cpcommit();

#pragma unroll 1
    for (int kt = 0; kt < nk; kt++) {
        if (kt + 1 < nk) {
            stage_g(sm + ((kt + 1) & 1) * GBUF, Ah, Al, lda, Bh, Bl, ldb, (kt + 1) * 32, tid);
            cpcommit();
            cpwait<1>();
        } else {
            cpwait<0>();
        }
        __syncthreads();
        const u32 base = sm + (kt & 1) * GBUF;
#pragma unroll
        for (int ks = 0; ks < 2; ks++) {
            u32 ah[4][4], al[4][4], bh[2][4], bl[2][4];
            const u32 aoff = base + (wm * 64 + lr) * 80 + ks * 32 + lc * 16;
#pragma unroll
            for (int mf = 0; mf < 4; mf++) {
                ldm4(ah[mf], aoff + mf * 1280);
                ldm4(al[mf], aoff + mf * 1280 + GMAT);
            }
            const u32 boff = base + 2 * GMAT + (wn * 32 + lr) * 80 + ks * 32 + lc * 16;
#pragma unroll
            for (int g = 0; g < 2; g++) {
                ldm4(bh[g], boff + g * 1280);
                ldm4(bl[g], boff + g * 1280 + GMAT);
            }
#pragma unroll
            for (int mf = 0; mf < 4; mf++)
#pragma unroll
                for (int nf = 0; nf < 4; nf++) {
                    const int g = nf >> 1, od = nf & 1;
                    mma_bf(c[mf][nf], ah[mf], bh[g][od], bh[g][od + 2]);
                    mma_bf(c[mf][nf], al[mf], bh[g][od], bh[g][od + 2]);
                    mma_bf(c[mf][nf], ah[mf], bl[g][od], bl[g][od + 2]);
                }
        }
        __syncthreads();
    }
}

// ============================================================
// hproj: batched QKV projections (one launch)
// ============================================================
__global__ __launch_bounds__(256) void hproj(
    const bf16* __restrict__ AhB, const bf16* __restrict__ AlB,
    const float* __restrict__ bq, const float* __restrict__ bk,
    const float* __restrict__ bv)
{
    extern __shared__ __align__(16) char smraw[];
    const u32 sm = smem_u32(smraw);
    const int s = blockIdx.z;
    const int bm = blockIdx.y << 7;
    const int bnG = blockIdx.x << 7;
    const int p = bnG >> 10, bnL = bnG & 1023;

    const float* bias = (p == 0) ? bq : (p == 1) ? bk : bv;
    bf16* oh = (p == 0) ? g_Qh[s] : (p == 1) ? g_Kh[s] : g_Vh[s];
    bf16* ol = (p == 0) ? g_Ql[s] : (p == 1) ? g_Kl[s] : g_Vl[s];

    float c[4][4][4];
#pragma unroll
    for (int i = 0; i < 4; i++)
#pragma unroll
        for (int j = 0; j < 4; j++)
#pragma unroll
            for (int k = 0; k < 4; k++) c[i][j][k] = 0.f;

    gemm_core(sm, AhB + s * NN + (size_t)bm * 1024, AlB + s * NN + (size_t)bm * 1024, 1024,
              &g_Wth[0][0] + (size_t)bnG * 1024, &g_Wtl[0][0] + (size_t)bnG * 1024, 1024, 32, c);

    const int wid = threadIdx.x >> 5, lane = threadIdx.x & 31;
    const int wm = wid >> 2, wn = wid & 3;
    const int rbase = bm + wm * 64 + (lane >> 2);
    const int cbase = bnL + wn * 32 + 2 * (lane & 3);
#pragma unroll
    for (int mf = 0; mf < 4; mf++)
#pragma unroll
        for (int nf = 0; nf < 4; nf++) {
            const int col = cbase + nf * 8;
            const float b0 = bias[col], b1 = bias[col + 1];
            const int row = rbase + mf * 16;
            wsplit2(oh, ol, (size_t)row * 1024 + col, c[mf][nf][0] + b0, c[mf][nf][1] + b1);
            wsplit2(oh, ol, (size_t)(row + 8) * 1024 + col, c[mf][nf][2] + b0, c[mf][nf][3] + b1);
        }
}

// ============================================================
// hout: batched output projection
// ============================================================
__global__ __launch_bounds__(256) void hout(
    const bf16* __restrict__ AOhB, const bf16* __restrict__ AOlB,
    const float* __restrict__ bo, float* __restrict__ out)
{
    extern __shared__ __align__(16) char smraw[];
    const u32 sm = smem_u32(smraw);
    const int s = blockIdx.z;
    const int bm = blockIdx.y << 7, bn = blockIdx.x << 7;

    float c[4][4][4];
#pragma unroll
    for (int i = 0; i < 4; i++)
#pragma unroll
        for (int j = 0; j < 4; j++)
#pragma unroll
            for (int k = 0; k < 4; k++) c[i][j][k] = 0.f;

    gemm_core(sm, AOhB + s * NN + (size_t)bm * 1024, AOlB + s * NN + (size_t)bm * 1024, 1024,
              &g_Wth[3][0] + (size_t)bn * 1024, &g_Wtl[3][0] + (size_t)bn * 1024, 1024, 32, c);

    float* outF = out + s * 1024;
    const int wid = threadIdx.x >> 5, lane = threadIdx.x & 31;
    const int wm = wid >> 2, wn = wid & 3;
    const int rbase = bm + wm * 64 + (lane >> 2);
    const int cbase = bn + wn * 32 + 2 * (lane & 3);
#pragma unroll
    for (int mf = 0; mf < 4; mf++)
#pragma unroll
        for (int nf = 0; nf < 4; nf++) {
            const int col = cbase + nf * 8;
            const float b0 = bo[col], b1 = bo[col + 1];
            const int row = rbase + mf * 16;
            *(float2*)(outF + (size_t)row * 3072 + col) =
                make_float2(c[mf][nf][0] + b0, c[mf][nf][1] + b1);
            *(float2*)(outF + (size_t)(row + 8) * 3072 + col) =
                make_float2(c[mf][nf][2] + b0, c[mf][nf][3] + b1);
        }
}

// ============================================================
// hattn: FULLY fused dual attention for all 3 output streams.
// CTA = (64 q-rows, one bh). Per k-tile of 64 keys:
//   s_H, s_T, s_R via MMA (3-term) in registers (computed ONCE),
//   p_o = exp((s_a+s_b)/16) -> bf16 hi/lo in smem,
//   O_o += P_o @ V_o via MMA (3-term). Normalize by row-sums at end.
// smem: Q[3][hl] persistent, K[3][hl], V[3][hl], P[3][hl], rowsums.
// 8 warps: 2m x 4n, warp tile 32x16. grid (16 qtiles, 128 bh).
// ============================================================
#define AROW 144
#define ATILE 9216        // 64*144
#define AQ 0
#define AK 55296
#define AV 110592
#define AP 165888
#define ASL 221184
#define ATTN_SMEM 221952

__device__ __forceinline__ void stage64(u32 dst, const bf16* __restrict__ src) {
    const int t = threadIdx.x;
    const int r0 = t >> 3, cc = t & 7, r1 = r0 + 32;
    cp16(dst + r0 * AROW + cc * 16, src + (size_t)r0 * 1024 + cc * 8);
    cp16(dst + r1 * AROW + cc * 16, src + (size_t)r1 * 1024 + cc * 8);
}

__global__ __launch_bounds__(256, 1) void hattn()
{
    extern __shared__ __align__(16) char smraw[];
    const u32 sm = smem_u32(smraw);
    float* sL = (float*)(smraw + ASL);

    const int tid = threadIdx.x, wid = tid >> 5, lane = tid & 31;
    const int bh = blockIdx.y, b = bh >> 4, h = bh & 15;
    const int i0 = blockIdx.x << 6;

    const int wm = wid & 1, wn = wid >> 1;       // 2m x 4n
    const int lr = lane & 15, lc = lane >> 4;

    if (tid < 192) sL[tid] = 0.f;

    const size_t qoff = ((size_t)((b << 10) + i0)) * 1024 + (h << 6);
    const size_t koff = ((size_t)(b << 10)) * 1024 + (h << 6);
    const bf16* Qp[6] = { g_Qh[0] + qoff, g_Ql[0] + qoff, g_Qh[1] + qoff,
                          g_Ql[1] + qoff, g_Qh[2] + qoff, g_Ql[2] + qoff };
    const bf16* Kp[6] = { g_Kh[0] + koff, g_Kl[0] + koff, g_Kh[1] + koff,
                          g_Kl[1] + koff, g_Kh[2] + koff, g_Kl[2] + koff };
    const bf16* Vp[6] = { g_Vh[0] + koff, g_Vl[0] + koff, g_Vh[1] + koff,
                          g_Vl[1] + koff, g_Vh[2] + koff, g_Vl[2] + koff };

    // prologue: group0 = {Q, K(0)}, group1 = {V(0)}
#pragma unroll
    for (int m = 0; m < 6; m++) stage64(sm + AQ + m * ATILE, Qp[m]);
#pragma unroll
    for (int m = 0; m < 6; m++) stage64(sm + AK + m * ATILE, Kp[m]);
    cpcommit();
#pragma unroll
    for (int m = 0; m < 6; m++) stage64(sm + AV + m * ATILE, Vp[m]);
    cpcommit();

    float co[3][2][2][4];
    float Lsum[3][4];
#pragma unroll
    for (int o = 0; o < 3; o++) {
#pragma unroll
        for (int i = 0; i < 4; i++) Lsum[o][i] = 0.f;
#pragma unroll
        for (int mf = 0; mf < 2; mf++)
#pragma unroll
            for (int nf = 0; nf < 2; nf++)
#pragma unroll
                for (int k = 0; k < 4; k++) co[o][mf][nf][k] = 0.f;
    }

#pragma unroll 1
    for (int kt = 0; kt < 16; kt++) {
        cpwait<1>();                 // Q + K(kt) ready (V(kt) may be in flight)
        __syncthreads();

        // ---- score MMAs: s_s = Q_s . K_s^T (3-term) ----
        float sc[3][2][2][4];
#pragma unroll
        for (int s3 = 0; s3 < 3; s3++)
#pragma unroll
            for (int mf = 0; mf < 2; mf++)
#pragma unroll
                for (int nf = 0; nf < 2; nf++)
#pragma unroll
                    for (int k = 0; k < 4; k++) sc[s3][mf][nf][k] = 0.f;

#pragma unroll
        for (int s3 = 0; s3 < 3; s3++) {
            const u32 qb = sm + AQ + (s3 * 2) * ATILE + (wm * 32 + lr) * AROW + lc * 16;
            const u32 kb = sm + AK + (s3 * 2) * ATILE + (wn * 16 + lr) * AROW + lc * 16;
#pragma unroll
            for (int ks = 0; ks < 4; ks++) {
                u32 qh[2][4], ql[2][4], kh[4], kl[4];
#pragma unroll
                for (int mf = 0; mf < 2; mf++) {
                    ldm4(qh[mf], qb + mf * 2304 + ks * 32);
                    ldm4(ql[mf], qb + mf * 2304 + ks * 32 + ATILE);
                }
                ldm4(kh, kb + ks * 32);
                ldm4(kl, kb + ks * 32 + ATILE);
#pragma unroll
                for (int mf = 0; mf < 2; mf++)
#pragma unroll
                    for (int nf = 0; nf < 2; nf++) {
                        mma_bf(sc[s3][mf][nf], qh[mf], kh[nf], kh[nf + 2]);
                        mma_bf(sc[s3][mf][nf], ql[mf], kh[nf], kh[nf + 2]);
                        mma_bf(sc[s3][mf][nf], qh[mf], kl[nf], kl[nf + 2]);
                    }
            }
        }
        __syncthreads();             // done reading K(kt)
        if (kt + 1 < 16) {
#pragma unroll
            for (int m = 0; m < 6; m++)
                stage64(sm + AK + m * ATILE, Kp[m] + (size_t)(kt + 1) * 65536);
        }
        cpcommit();                  // group {K(kt+1)} (possibly empty)

        // ---- p = exp((s_a + s_b)/16), split, store to P smem ----
#pragma unroll
        for (int o = 0; o < 3; o++) {
            const int sa = (o == 0) ? 1 : 0;
            const int sb = (o == 2) ? 1 : 2;
#pragma unroll
            for (int mf = 0; mf < 2; mf++)
#pragma unroll
                for (int nf = 0; nf < 2; nf++) {
                    const float p0 = __expf((sc[sa][mf][nf][0] + sc[sb][mf][nf][0]) * 0.0625f);
                    const float p1 = __expf((sc[sa][mf][nf][1] + sc[sb][mf][nf][1]) * 0.0625f);
                    const float p2 = __expf((sc[sa][mf][nf][2] + sc[sb][mf][nf][2]) * 0.0625f);
                    const float p3 = __expf((sc[sa][mf][nf][3] + sc[sb][mf][nf][3]) * 0.0625f);
                    Lsum[o][mf * 2 + 0] += p0 + p1;
                    Lsum[o][mf * 2 + 1] += p2 + p3;
                    bf16 h0 = __float2bfloat16(p0); const float l0 = p0 - __bfloat162float(h0);
                    bf16 h1 = __float2bfloat16(p1); const float l1 = p1 - __bfloat162float(h1);
                    bf16 h2 = __float2bfloat16(p2); const float l2 = p2 - __bfloat162float(h2);
                    bf16 h3 = __float2bfloat16(p3); const float l3 = p3 - __bfloat162float(h3);
                    const int row = wm * 32 + mf * 16 + (lane >> 2);
                    const int col = wn * 16 + nf * 8 + 2 * (lane & 3);
                    const u32 ad = sm + AP + (o * 2) * ATILE + row * AROW + col * 2;
                    __nv_bfloat162 t01; t01.x = h0; t01.y = h1;
                    __nv_bfloat162 t23; t23.x = h2; t23.y = h3;
                    sts32(ad,                 *(u32*)&t01);
                    sts32(ad + 8 * AROW,      *(u32*)&t23);
                    sts32(ad + ATILE,             packbf(l0, l1));
                    sts32(ad + ATILE + 8 * AROW,  packbf(l2, l3));
                }
        }

        cpwait<1>();                 // V(kt) ready (K(kt+1) may be in flight)
        __syncthreads();             // P visible

        // ---- PV MMAs: O_o += P_o @ V_o (3-term) ----
#pragma unroll
        for (int o = 0; o < 3; o++) {
            const u32 pb = sm + AP + (o * 2) * ATILE + (wm * 32 + lr) * AROW + lc * 16;
            const u32 vb = sm + AV + (o * 2) * ATILE + lr * AROW + wn * 32 + lc * 16;
#pragma unroll
            for (int ks = 0; ks < 4; ks++) {
                u32 ph[2][4], pl[2][4], vh[4], vl[4];
#pragma unroll
                for (int mf = 0; mf < 2; mf++) {
                    ldm4(ph[mf], pb + mf * 2304 + ks * 32);
                    ldm4(pl[mf], pb + mf * 2304 + ks * 32 + ATILE);
                }
                ldm4t(vh, vb + ks * 16 * AROW);
                ldm4t(vl, vb + ks * 16 * AROW + ATILE);
#pragma unroll
                for (int mf = 0; mf < 2; mf++)
#pragma unroll
                    for (int nf = 0; nf < 2; nf++) {
                        mma_bf(co[o][mf][nf], ph[mf], vh[2 * nf], vh[2 * nf + 1]);
                        mma_bf(co[o][mf][nf], pl[mf], vh[2 * nf], vh[2 * nf + 1]);
                        mma_bf(co[o][mf][nf], ph[mf], vl[2 * nf], vl[2 * nf + 1]);
                    }
            }
        }
        __syncthreads();             // done reading V(kt) and P
        if (kt + 1 < 16) {
#pragma unroll
            for (int m = 0; m < 6; m++)
                stage64(sm + AV + m * ATILE, Vp[m] + (size_t)(kt + 1) * 65536);
        }
        cpcommit();                  // group {V(kt+1)} (possibly empty)
    }

    // ---- row-sum reduction into sL ----
#pragma unroll
    for (int o = 0; o < 3; o++)
#pragma unroll
        for (int sl = 0; sl < 4; sl++) {
            float v = Lsum[o][sl];
            v += __shfl_xor_sync(0xffffffffu, v, 1);
            v += __shfl_xor_sync(0xffffffffu, v, 2);
            if ((lane & 3) == 0) {
                const int row = wm * 32 + (sl >> 1) * 16 + (lane >> 2) + (sl & 1) * 8;
                atomicAdd(&sL[o * 64 + row], v);
            }
        }
    __syncthreads();

    // ---- epilogue: normalize + write AO split ----
#pragma unroll
    for (int o = 0; o < 3; o++) {
        bf16* AH = g_AOh[o];
        bf16* AL = g_AOl[o];
#pragma unroll
        for (int mf = 0; mf < 2; mf++)
#pragma unroll
            for (int nf = 0; nf < 2; nf++) {
                const int rl0 = wm * 32 + mf * 16 + (lane >> 2);
                const int rl1 = rl0 + 8;
                const int cl = wn * 16 + nf * 8 + 2 * (lane & 3);
                const float iv0 = 1.0f / sL[o * 64 + rl0];
                const float iv1 = 1.0f / sL[o * 64 + rl1];
                const size_t ga = ((size_t)((b << 10) + i0 + rl0)) * 1024 + (h << 6) + cl;
                const size_t gb2 = ((size_t)((b << 10) + i0 + rl1)) * 1024 + (h << 6) + cl;
                wsplit2(AH, AL, ga,  co[o][mf][nf][0] * iv0, co[o][mf][nf][1] * iv0);
                wsplit2(AH, AL, gb2, co[o][mf][nf][2] * iv1, co[o][mf][nf][3] * iv1);
            }
    }
}

// ============================================================
// prep kernels
// ============================================================
__global__ __launch_bounds__(256) void split_f32(
    const float* __restrict__ src, int stride,
    bf16* __restrict__ hi, bf16* __restrict__ lo)
{
    size_t idx = ((size_t)blockIdx.x * 256 + threadIdx.x) * 4;
    int row = (int)(idx >> 10), col = (int)(idx & 1023);
    float4 v = *(const float4*)(src + (size_t)row * stride + col);
    bf16 h0 = __float2bfloat16(v.x); bf16 l0 = __float2bfloat16(v.x - __bfloat162float(h0));
    bf16 h1 = __float2bfloat16(v.y); bf16 l1 = __float2bfloat16(v.y - __bfloat162float(h1));
    bf16 h2 = __float2bfloat16(v.z); bf16 l2 = __float2bfloat16(v.z - __bfloat162float(h2));
    bf16 h3 = __float2bfloat16(v.w); bf16 l3 = __float2bfloat16(v.w - __bfloat162float(h3));
    __nv_bfloat162 a; a.x = h0; a.y = h1;
    __nv_bfloat162 bb; bb.x = h2; bb.y = h3;
    __nv_bfloat162 cc; cc.x = l0; cc.y = l1;
    __nv_bfloat162 d; d.x = l2; d.y = l3;
    ((__nv_bfloat162*)(hi + idx))[0] = a;
    ((__nv_bfloat162*)(hi + idx))[1] = bb;
    ((__nv_bfloat162*)(lo + idx))[0] = cc;
    ((__nv_bfloat162*)(lo + idx))[1] = d;
}

__global__ __launch_bounds__(256) void transposeAll(
    const float* __restrict__ W0, const float* __restrict__ W1,
    const float* __restrict__ W2, const float* __restrict__ W3)
{
    __shared__ float t[32][33];
    const int w = blockIdx.z;
    const float* W = (w == 0) ? W0 : (w == 1) ? W1 : (w == 2) ? W2 : W3;
    bf16* Th = &g_Wth[0][0] + (size_t)w * NW;
    bf16* Tl = &g_Wtl[0][0] + (size_t)w * NW;
    int n0 = blockIdx.x << 5, k0 = blockIdx.y << 5;
    int tx = threadIdx.x, ty = threadIdx.y;
    for (int r = ty; r < 32; r += 8)
        t[r][tx] = W[(size_t)(k0 + r) * 1024 + n0 + tx];
    __syncthreads();
    for (int r = ty; r < 32; r += 8) {
        float v = t[tx][r];
        bf16 hh = __float2bfloat16(v);
        bf16 ll = __float2bfloat16(v - __bfloat162float(hh));
        Th[(size_t)(n0 + r) * 1024 + k0 + tx] = hh;
        Tl[(size_t)(n0 + r) * 1024 + k0 + tx] = ll;
    }
}

// ============================================================
// Launch  (order chosen so ncu -s 5 -c 1 captures hattn)
// ============================================================
extern "C" void kernel_launch(void* const* d_in, const int* in_sizes, int n_in,
                              void* d_out, int out_size)
{
    const float* x  = (const float*)d_in[0];
    const float* Wq = (const float*)d_in[1];
    const float* bq = (const float*)d_in[2];
    const float* Wk = (const float*)d_in[3];
    const float* bk = (const float*)d_in[4];
    const float* Wv = (const float*)d_in[5];
    const float* bv = (const float*)d_in[6];
    const float* Wo = (const float*)d_in[7];
    const float* bo = (const float*)d_in[8];
    float* out = (float*)d_out;

    static bool attr_set = false;
    if (!attr_set) {
        cudaFuncSetAttribute(hproj, cudaFuncAttributeMaxDynamicSharedMemorySize, GEMM_SMEM);
        cudaFuncSetAttribute(hout, cudaFuncAttributeMaxDynamicSharedMemorySize, GEMM_SMEM);
        cudaFuncSetAttribute(hattn, cudaFuncAttributeMaxDynamicSharedMemorySize, ATTN_SMEM);
        attr_set = true;
    }

    bf16 *Ah, *Al, *AOh, *AOl;
    cudaGetSymbolAddress((void**)&Ah, g_Ah);   cudaGetSymbolAddress((void**)&Al, g_Al);
    cudaGetSymbolAddress((void**)&AOh, g_AOh); cudaGetSymbolAddress((void**)&AOl, g_AOl);

    // launches 0-2: input splits
    for (int s = 0; s < 3; s++)
        split_f32<<<8192, 256>>>(x + s * 1024, 3072, Ah + s * NN, Al + s * NN);
    // launch 3: all weight transpose-splits
    transposeAll<<<dim3(32, 32, 4), dim3(32, 8)>>>(Wq, Wk, Wv, Wo);
    // launch 4: batched QKV projections
    hproj<<<dim3(24, 64, 3), 256, GEMM_SMEM>>>(Ah, Al, bq, bk, bv);
    // launch 5: fully fused dual attention (ncu lands here)
    hattn<<<dim3(16, 128), 256, ATTN_SMEM>>>();
    // launch 6: batched output projection
    hout<<<dim3(8, 64, 3), 256, GEMM_SMEM>>>(AOh, AOl, bo, out);
}

// round 9
// speedup vs baseline: 4.4839x; 1.0734x over previous
#include <cuda_runtime.h>
#include <cuda_bf16.h>
#include <cuda_fp16.h>
#include <cstdint>

typedef __nv_bfloat16 bf16;
typedef unsigned int u32;

#define NN 8388608ULL      // 8192*1024
#define NW 1048576ULL      // 1024*1024

// ---------------- global scratch ----------------
__device__ bf16 g_Ah[3][NN], g_Al[3][NN];        // x split
__device__ bf16 g_Qh[3][NN], g_Ql[3][NN];
__device__ bf16 g_Kh[3][NN], g_Kl[3][NN];
__device__ __half g_Vh[3][NN], g_Vl[3][NN];      // V split in fp16 (for fp16 PV mma)
__device__ bf16 g_AOh[3][NN], g_AOl[3][NN];      // attention out split
__device__ bf16 g_Wth[4][NW], g_Wtl[4][NW];      // W^T splits [q,k,v,o] contiguous

// ---------------- PTX helpers ----------------
__device__ __forceinline__ u32 smem_u32(const void* p) {
    u32 a;
    asm("{ .reg .u64 t; cvta.to.shared.u64 t, %1; cvt.u32.u64 %0, t; }" : "=r"(a) : "l"(p));
    return a;
}
__device__ __forceinline__ void cp16(u32 d, const void* s) {
    asm volatile("cp.async.cg.shared.global [%0], [%1], 16;" :: "r"(d), "l"(s));
}
__device__ __forceinline__ void cpcommit() { asm volatile("cp.async.commit_group;"); }
template<int N> __device__ __forceinline__ void cpwait() {
    asm volatile("cp.async.wait_group %0;" :: "n"(N));
}
__device__ __forceinline__ void ldm4(u32* r, u32 a) {
    asm volatile("ldmatrix.sync.aligned.m8n8.x4.shared.b16 {%0,%1,%2,%3}, [%4];"
                 : "=r"(r[0]), "=r"(r[1]), "=r"(r[2]), "=r"(r[3]) : "r"(a));
}
__device__ __forceinline__ void ldm4t(u32* r, u32 a) {
    asm volatile("ldmatrix.sync.aligned.m8n8.x4.trans.shared.b16 {%0,%1,%2,%3}, [%4];"
                 : "=r"(r[0]), "=r"(r[1]), "=r"(r[2]), "=r"(r[3]) : "r"(a));
}
__device__ __forceinline__ void mma_bf(float* c, const u32* a, u32 b0, u32 b1) {
    asm volatile(
        "mma.sync.aligned.m16n8k16.row.col.f32.bf16.bf16.f32 "
        "{%0,%1,%2,%3}, {%4,%5,%6,%7}, {%8,%9}, {%0,%1,%2,%3};"
        : "+f"(c[0]), "+f"(c[1]), "+f"(c[2]), "+f"(c[3])
        : "r"(a[0]), "r"(a[1]), "r"(a[2]), "r"(a[3]), "r"(b0), "r"(b1));
}
__device__ __forceinline__ void mma_fp(float* c, const u32* a, u32 b0, u32 b1) {
    asm volatile(
        "mma.sync.aligned.m16n8k16.row.col.f32.f16.f16.f32 "
        "{%0,%1,%2,%3}, {%4,%5,%6,%7}, {%8,%9}, {%0,%1,%2,%3};"
        : "+f"(c[0]), "+f"(c[1]), "+f"(c[2]), "+f"(c[3])
        : "r"(a[0]), "r"(a[1]), "r"(a[2]), "r"(a[3]), "r"(b0), "r"(b1));
}
__device__ __forceinline__ void wsplit2(bf16* H, bf16* L, size_t off, float v0, float v1) {
    bf16 h0 = __float2bfloat16(v0); bf16 l0 = __float2bfloat16(v0 - __bfloat162float(h0));
    bf16 h1 = __float2bfloat16(v1); bf16 l1 = __float2bfloat16(v1 - __bfloat162float(h1));
    __nv_bfloat162 hh; hh.x = h0; hh.y = h1;
    __nv_bfloat162 ll; ll.x = l0; ll.y = l1;
    *(__nv_bfloat162*)(H + off) = hh;
    *(__nv_bfloat162*)(L + off) = ll;
}
__device__ __forceinline__ void wsplit2h(__half* H, __half* L, size_t off, float v0, float v1) {
    __half h0 = __float2half_rn(v0); __half l0 = __float2half_rn(v0 - __half2float(h0));
    __half h1 = __float2half_rn(v1); __half l1 = __float2half_rn(v1 - __half2float(h1));
    __half2 hh; hh.x = h0; hh.y = h1;
    __half2 ll; ll.x = l0; ll.y = l1;
    *(__half2*)(H + off) = hh;
    *(__half2*)(L + off) = ll;
}
__device__ __forceinline__ void sts32(u32 a, u32 v) {
    asm volatile("st.shared.b32 [%0], %1;" :: "r"(a), "r"(v) : "memory");
}

// ============================================================
// Shared GEMM core: 128x128 tile, BK=32, 256 thr, 8 warps (2m x 4n),
// warp 64x32, bf16 3-term split, cp.async double buffer.
// ============================================================
#define GMAT 10240
#define GBUF 40960
#define GEMM_SMEM 81920

__device__ __forceinline__ void stage_g(u32 sm,
    const bf16* __restrict__ Ah, const bf16* __restrict__ Al, int lda,
    const bf16* __restrict__ Bh, const bf16* __restrict__ Bl, int ldb,
    int k0, int tid)
{
    const int r = tid >> 2, cc = tid & 3;
    const u32 so = r * 80 + cc * 16;
    const int co = k0 + cc * 8;
    cp16(sm + so,                 Ah + (size_t)r * lda + co);
    cp16(sm + so + 5120,          Ah + (size_t)(r + 64) * lda + co);
    cp16(sm + GMAT + so,          Al + (size_t)r * lda + co);
    cp16(sm + GMAT + so + 5120,   Al + (size_t)(r + 64) * lda + co);
    cp16(sm + 2*GMAT + so,        Bh + (size_t)r * ldb + co);
    cp16(sm + 2*GMAT + so + 5120, Bh + (size_t)(r + 64) * ldb + co);
    cp16(sm + 3*GMAT + so,        Bl + (size_t)r * ldb + co);
    cp16(sm + 3*GMAT + so + 5120, Bl + (size_t)(r + 64) * ldb + co);
}

__device__ __forceinline__ void gemm_core(u32 sm,
    const bf16* __restrict__ Ah, const bf16* __restrict__ Al, int lda,
    const bf16* __restrict__ Bh, const bf16* __restrict__ Bl, int ldb,
    int nk, float c[4][4][4])
{
    const int tid = threadIdx.x, wid = tid >> 5, lane = tid & 31;
    const int wm = wid >> 2, wn = wid & 3;
    const int lr = lane & 15, lc = lane >> 4;

    stage_g(sm, Ah, Al, lda, Bh, Bl, ldb, 0, tid);
    cpcommit();

#pragma unroll 1
    for (int kt = 0; kt < nk; kt++) {
        if (kt + 1 < nk) {
            stage_g(sm + ((kt + 1) & 1) * GBUF, Ah, Al, lda, Bh, Bl, ldb, (kt + 1) * 32, tid);
            cpcommit();
            cpwait<1>();
        } else {
            cpwait<0>();
        }
        __syncthreads();
        const u32 base = sm + (kt & 1) * GBUF;
#pragma unroll
        for (int ks = 0; ks < 2; ks++) {
            u32 ah[4][4], al[4][4], bh[2][4], bl[2][4];
            const u32 aoff = base + (wm * 64 + lr) * 80 + ks * 32 + lc * 16;
#pragma unroll
            for (int mf = 0; mf < 4; mf++) {
                ldm4(ah[mf], aoff + mf * 1280);
                ldm4(al[mf], aoff + mf * 1280 + GMAT);
            }
            const u32 boff = base + 2 * GMAT + (wn * 32 + lr) * 80 + ks * 32 + lc * 16;
#pragma unroll
            for (int g = 0; g < 2; g++) {
                ldm4(bh[g], boff + g * 1280);
                ldm4(bl[g], boff + g * 1280 + GMAT);
            }
#pragma unroll
            for (int mf = 0; mf < 4; mf++)
#pragma unroll
                for (int nf = 0; nf < 4; nf++) {
                    const int g = nf >> 1, od = nf & 1;
                    mma_bf(c[mf][nf], ah[mf], bh[g][od], bh[g][od + 2]);
                    mma_bf(c[mf][nf], al[mf], bh[g][od], bh[g][od + 2]);
                    mma_bf(c[mf][nf], ah[mf], bl[g][od], bl[g][od + 2]);
                }
        }
        __syncthreads();
    }
}

// ============================================================
// hproj: batched QKV projections. q,k -> bf16 split; v -> fp16 split.
// ============================================================
__global__ __launch_bounds__(256) void hproj(
    const bf16* __restrict__ AhB, const bf16* __restrict__ AlB,
    const float* __restrict__ bq, const float* __restrict__ bk,
    const float* __restrict__ bv)
{
    extern __shared__ __align__(16) char smraw[];
    const u32 sm = smem_u32(smraw);
    const int s = blockIdx.z;
    const int bm = blockIdx.y << 7;
    const int bnG = blockIdx.x << 7;
    const int p = bnG >> 10, bnL = bnG & 1023;

    const float* bias = (p == 0) ? bq : (p == 1) ? bk : bv;

    float c[4][4][4];
#pragma unroll
    for (int i = 0; i < 4; i++)
#pragma unroll
        for (int j = 0; j < 4; j++)
#pragma unroll
            for (int k = 0; k < 4; k++) c[i][j][k] = 0.f;

    gemm_core(sm, AhB + s * NN + (size_t)bm * 1024, AlB + s * NN + (size_t)bm * 1024, 1024,
              &g_Wth[0][0] + (size_t)bnG * 1024, &g_Wtl[0][0] + (size_t)bnG * 1024, 1024, 32, c);

    const int wid = threadIdx.x >> 5, lane = threadIdx.x & 31;
    const int wm = wid >> 2, wn = wid & 3;
    const int rbase = bm + wm * 64 + (lane >> 2);
    const int cbase = bnL + wn * 32 + 2 * (lane & 3);

    if (p == 2) {
        __half* oh = g_Vh[s];
        __half* ol = g_Vl[s];
#pragma unroll
        for (int mf = 0; mf < 4; mf++)
#pragma unroll
            for (int nf = 0; nf < 4; nf++) {
                const int col = cbase + nf * 8;
                const float b0 = bias[col], b1 = bias[col + 1];
                const int row = rbase + mf * 16;
                wsplit2h(oh, ol, (size_t)row * 1024 + col, c[mf][nf][0] + b0, c[mf][nf][1] + b1);
                wsplit2h(oh, ol, (size_t)(row + 8) * 1024 + col, c[mf][nf][2] + b0, c[mf][nf][3] + b1);
            }
    } else {
        bf16* oh = (p == 0) ? g_Qh[s] : g_Kh[s];
        bf16* ol = (p == 0) ? g_Ql[s] : g_Kl[s];
#pragma unroll
        for (int mf = 0; mf < 4; mf++)
#pragma unroll
            for (int nf = 0; nf < 4; nf++) {
                const int col = cbase + nf * 8;
                const float b0 = bias[col], b1 = bias[col + 1];
                const int row = rbase + mf * 16;
                wsplit2(oh, ol, (size_t)row * 1024 + col, c[mf][nf][0] + b0, c[mf][nf][1] + b1);
                wsplit2(oh, ol, (size_t)(row + 8) * 1024 + col, c[mf][nf][2] + b0, c[mf][nf][3] + b1);
            }
    }
}

// ============================================================
// hout: batched output projection
// ============================================================
__global__ __launch_bounds__(256) void hout(
    const bf16* __restrict__ AOhB, const bf16* __restrict__ AOlB,
    const float* __restrict__ bo, float* __restrict__ out)
{
    extern __shared__ __align__(16) char smraw[];
    const u32 sm = smem_u32(smraw);
    const int s = blockIdx.z;
    const int bm = blockIdx.y << 7, bn = blockIdx.x << 7;

    float c[4][4][4];
#pragma unroll
    for (int i = 0; i < 4; i++)
#pragma unroll
        for (int j = 0; j < 4; j++)
#pragma unroll
            for (int k = 0; k < 4; k++) c[i][j][k] = 0.f;

    gemm_core(sm, AOhB + s * NN + (size_t)bm * 1024, AOlB + s * NN + (size_t)bm * 1024, 1024,
              &g_Wth[3][0] + (size_t)bn * 1024, &g_Wtl[3][0] + (size_t)bn * 1024, 1024, 32, c);

    float* outF = out + s * 1024;
    const int wid = threadIdx.x >> 5, lane = threadIdx.x & 31;
    const int wm = wid >> 2, wn = wid & 3;
    const int rbase = bm + wm * 64 + (lane >> 2);
    const int cbase = bn + wn * 32 + 2 * (lane & 3);
#pragma unroll
    for (int mf = 0; mf < 4; mf++)
#pragma unroll
        for (int nf = 0; nf < 4; nf++) {
            const int col = cbase + nf * 8;
            const float b0 = bo[col], b1 = bo[col + 1];
            const int row = rbase + mf * 16;
            *(float2*)(outF + (size_t)row * 3072 + col) =
                make_float2(c[mf][nf][0] + b0, c[mf][nf][1] + b1);
            *(float2*)(outF + (size_t)(row + 8) * 3072 + col) =
                make_float2(c[mf][nf][2] + b0, c[mf][nf][3] + b1);
        }
}

// ============================================================
// hattn: fully fused dual attention, all 3 output streams per CTA.
// Scores: bf16 3-term (Q/K hi+lo). P: fp16 (11-bit mantissa).
// PV: fp16 mma, 2-term P@(Vh+Vl) with V fp16 hi/lo (V exact).
// smem: Q[3][hl] bf16, K[3][hl] bf16, V[3][hl] fp16, P[3] fp16, rowsums.
// ============================================================
#define AROW 144
#define ATILE 9216        // 64*144
#define AQ 0
#define AK 55296
#define AV 110592
#define AP 165888         // 3 tiles (fp16 p)
#define ASL 193536
#define ATTN_SMEM 194304

__device__ __forceinline__ void stage64(u32 dst, const void* __restrict__ src16) {
    const char* src = (const char*)src16;
    const int t = threadIdx.x;
    const int r0 = t >> 3, cc = t & 7, r1 = r0 + 32;
    cp16(dst + r0 * AROW + cc * 16, src + (size_t)r0 * 2048 + cc * 16);
    cp16(dst + r1 * AROW + cc * 16, src + (size_t)r1 * 2048 + cc * 16);
}

__global__ __launch_bounds__(256, 1) void hattn()
{
    extern __shared__ __align__(16) char smraw[];
    const u32 sm = smem_u32(smraw);
    float* sL = (float*)(smraw + ASL);

    const int tid = threadIdx.x, wid = tid >> 5, lane = tid & 31;
    const int bh = blockIdx.y, b = bh >> 4, h = bh & 15;
    const int i0 = blockIdx.x << 6;

    const int wm = wid & 1, wn = wid >> 1;       // 2m x 4n
    const int lr = lane & 15, lc = lane >> 4;

    if (tid < 192) sL[tid] = 0.f;

    const size_t qoff = ((size_t)((b << 10) + i0)) * 1024 + (h << 6);
    const size_t koff = ((size_t)(b << 10)) * 1024 + (h << 6);
    const void* Qp[6] = { g_Qh[0] + qoff, g_Ql[0] + qoff, g_Qh[1] + qoff,
                          g_Ql[1] + qoff, g_Qh[2] + qoff, g_Ql[2] + qoff };
    const void* Kp[6] = { g_Kh[0] + koff, g_Kl[0] + koff, g_Kh[1] + koff,
                          g_Kl[1] + koff, g_Kh[2] + koff, g_Kl[2] + koff };
    const void* Vp[6] = { g_Vh[0] + koff, g_Vl[0] + koff, g_Vh[1] + koff,
                          g_Vl[1] + koff, g_Vh[2] + koff, g_Vl[2] + koff };

    // prologue: group0 = {Q, K(0)}, group1 = {V(0)}
#pragma unroll
    for (int m = 0; m < 6; m++) stage64(sm + AQ + m * ATILE, Qp[m]);
#pragma unroll
    for (int m = 0; m < 6; m++) stage64(sm + AK + m * ATILE, Kp[m]);
    cpcommit();
#pragma unroll
    for (int m = 0; m < 6; m++) stage64(sm + AV + m * ATILE, Vp[m]);
    cpcommit();

    float co[3][2][2][4];
    float Lsum[3][4];
#pragma unroll
    for (int o = 0; o < 3; o++) {
#pragma unroll
        for (int i = 0; i < 4; i++) Lsum[o][i] = 0.f;
#pragma unroll
        for (int mf = 0; mf < 2; mf++)
#pragma unroll
            for (int nf = 0; nf < 2; nf++)
#pragma unroll
                for (int k = 0; k < 4; k++) co[o][mf][nf][k] = 0.f;
    }

#pragma unroll 1
    for (int kt = 0; kt < 16; kt++) {
        cpwait<1>();                 // Q + K(kt) ready
        __syncthreads();

        // ---- score MMAs: s_s = Q_s . K_s^T (bf16 3-term) ----
        float sc[3][2][2][4];
#pragma unroll
        for (int s3 = 0; s3 < 3; s3++)
#pragma unroll
            for (int mf = 0; mf < 2; mf++)
#pragma unroll
                for (int nf = 0; nf < 2; nf++)
#pragma unroll
                    for (int k = 0; k < 4; k++) sc[s3][mf][nf][k] = 0.f;

#pragma unroll
        for (int s3 = 0; s3 < 3; s3++) {
            const u32 qb = sm + AQ + (s3 * 2) * ATILE + (wm * 32 + lr) * AROW + lc * 16;
            const u32 kb = sm + AK + (s3 * 2) * ATILE + (wn * 16 + lr) * AROW + lc * 16;
#pragma unroll
            for (int ks = 0; ks < 4; ks++) {
                u32 qh[2][4], ql[2][4], kh[4], kl[4];
#pragma unroll
                for (int mf = 0; mf < 2; mf++) {
                    ldm4(qh[mf], qb + mf * 2304 + ks * 32);
                    ldm4(ql[mf], qb + mf * 2304 + ks * 32 + ATILE);
                }
                ldm4(kh, kb + ks * 32);
                ldm4(kl, kb + ks * 32 + ATILE);
#pragma unroll
                for (int mf = 0; mf < 2; mf++)
#pragma unroll
                    for (int nf = 0; nf < 2; nf++) {
                        mma_bf(sc[s3][mf][nf], qh[mf], kh[nf], kh[nf + 2]);
                        mma_bf(sc[s3][mf][nf], ql[mf], kh[nf], kh[nf + 2]);
                        mma_bf(sc[s3][mf][nf], qh[mf], kl[nf], kl[nf + 2]);
                    }
            }
        }
        __syncthreads();             // done reading K(kt)
        if (kt + 1 < 16) {
#pragma unroll
            for (int m = 0; m < 6; m++)
                stage64(sm + AK + m * ATILE, (const char*)Kp[m] + (size_t)(kt + 1) * 131072);
        }
        cpcommit();                  // group {K(kt+1)}

        // ---- p = exp((s_a + s_b)/16) -> fp16, to P smem ----
#pragma unroll
        for (int o = 0; o < 3; o++) {
            const int sa = (o == 0) ? 1 : 0;
            const int sb = (o == 2) ? 1 : 2;
#pragma unroll
            for (int mf = 0; mf < 2; mf++)
#pragma unroll
                for (int nf = 0; nf < 2; nf++) {
                    const float p0 = __expf((sc[sa][mf][nf][0] + sc[sb][mf][nf][0]) * 0.0625f);
                    const float p1 = __expf((sc[sa][mf][nf][1] + sc[sb][mf][nf][1]) * 0.0625f);
                    const float p2 = __expf((sc[sa][mf][nf][2] + sc[sb][mf][nf][2]) * 0.0625f);
                    const float p3 = __expf((sc[sa][mf][nf][3] + sc[sb][mf][nf][3]) * 0.0625f);
                    Lsum[o][mf * 2 + 0] += p0 + p1;
                    Lsum[o][mf * 2 + 1] += p2 + p3;
                    const int row = wm * 32 + mf * 16 + (lane >> 2);
                    const int col = wn * 16 + nf * 8 + 2 * (lane & 3);
                    const u32 ad = sm + AP + o * ATILE + row * AROW + col * 2;
                    __half2 t01; t01.x = __float2half_rn(p0); t01.y = __float2half_rn(p1);
                    __half2 t23; t23.x = __float2half_rn(p2); t23.y = __float2half_rn(p3);
                    sts32(ad,            *(u32*)&t01);
                    sts32(ad + 8 * AROW, *(u32*)&t23);
                }
        }

        cpwait<1>();                 // V(kt) ready
        __syncthreads();             // P visible

        // ---- PV MMAs (fp16): O_o += P_o @ (V_hi + V_lo) ----
#pragma unroll
        for (int o = 0; o < 3; o++) {
            const u32 pb = sm + AP + o * ATILE + (wm * 32 + lr) * AROW + lc * 16;
            const u32 vb = sm + AV + (o * 2) * ATILE + lr * AROW + wn * 32 + lc * 16;
#pragma unroll
            for (int ks = 0; ks < 4; ks++) {
                u32 ph[2][4], vh[4], vl[4];
#pragma unroll
                for (int mf = 0; mf < 2; mf++)
                    ldm4(ph[mf], pb + mf * 2304 + ks * 32);
                ldm4t(vh, vb + ks * 16 * AROW);
                ldm4t(vl, vb + ks * 16 * AROW + ATILE);
#pragma unroll
                for (int mf = 0; mf < 2; mf++)
#pragma unroll
                    for (int nf = 0; nf < 2; nf++) {
                        mma_fp(co[o][mf][nf], ph[mf], vh[2 * nf], vh[2 * nf + 1]);
                        mma_fp(co[o][mf][nf], ph[mf], vl[2 * nf], vl[2 * nf + 1]);
                    }
            }
        }
        __syncthreads();             // done reading V(kt) and P
        if (kt + 1 < 16) {
#pragma unroll
            for (int m = 0; m < 6; m++)
                stage64(sm + AV + m * ATILE, (const char*)Vp[m] + (size_t)(kt + 1) * 131072);
        }
        cpcommit();                  // group {V(kt+1)}
    }

    // ---- row-sum reduction into sL ----
#pragma unroll
    for (int o = 0; o < 3; o++)
#pragma unroll
        for (int sl = 0; sl < 4; sl++) {
            float v = Lsum[o][sl];
            v += __shfl_xor_sync(0xffffffffu, v, 1);
            v += __shfl_xor_sync(0xffffffffu, v, 2);
            if ((lane & 3) == 0) {
                const int row = wm * 32 + (sl >> 1) * 16 + (lane >> 2) + (sl & 1) * 8;
                atomicAdd(&sL[o * 64 + row], v);
            }
        }
    __syncthreads();

    // ---- epilogue: normalize + write AO split (bf16) ----
#pragma unroll
    for (int o = 0; o < 3; o++) {
        bf16* AH = g_AOh[o];
        bf16* AL = g_AOl[o];
#pragma unroll
        for (int mf = 0; mf < 2; mf++)
#pragma unroll
            for (int nf = 0; nf < 2; nf++) {
                const int rl0 = wm * 32 + mf * 16 + (lane >> 2);
                const int rl1 = rl0 + 8;
                const int cl = wn * 16 + nf * 8 + 2 * (lane & 3);
                const float iv0 = 1.0f / sL[o * 64 + rl0];
                const float iv1 = 1.0f / sL[o * 64 + rl1];
                const size_t ga = ((size_t)((b << 10) + i0 + rl0)) * 1024 + (h << 6) + cl;
                const size_t gb2 = ((size_t)((b << 10) + i0 + rl1)) * 1024 + (h << 6) + cl;
                wsplit2(AH, AL, ga,  co[o][mf][nf][0] * iv0, co[o][mf][nf][1] * iv0);
                wsplit2(AH, AL, gb2, co[o][mf][nf][2] * iv1, co[o][mf][nf][3] * iv1);
            }
    }
}

// ============================================================
// split_all: all 3 stream splits in one launch
// ============================================================
__global__ __launch_bounds__(256) void split_all(const float* __restrict__ x)
{
    const size_t gid = (size_t)blockIdx.x * 256 + threadIdx.x;
    const int s = (int)(gid >> 21);
    const size_t t = gid & 2097151ULL;
    const size_t idx = t * 4;
    const int m = (int)(idx >> 10), col = (int)(idx & 1023);
    const float4 v = *(const float4*)(x + ((size_t)m * 3 + s) * 1024 + col);
    bf16* hi = &g_Ah[0][0] + s * NN + idx;
    bf16* lo = &g_Al[0][0] + s * NN + idx;
    bf16 h0 = __float2bfloat16(v.x); bf16 l0 = __float2bfloat16(v.x - __bfloat162float(h0));
    bf16 h1 = __float2bfloat16(v.y); bf16 l1 = __float2bfloat16(v.y - __bfloat162float(h1));
    bf16 h2 = __float2bfloat16(v.z); bf16 l2 = __float2bfloat16(v.z - __bfloat162float(h2));
    bf16 h3 = __float2bfloat16(v.w); bf16 l3 = __float2bfloat16(v.w - __bfloat162float(h3));
    __nv_bfloat162 a; a.x = h0; a.y = h1;
    __nv_bfloat162 bb; bb.x = h2; bb.y = h3;
    __nv_bfloat162 cc; cc.x = l0; cc.y = l1;
    __nv_bfloat162 d; d.x = l2; d.y = l3;
    ((__nv_bfloat162*)hi)[0] = a;
    ((__nv_bfloat162*)hi)[1] = bb;
    ((__nv_bfloat162*)lo)[0] = cc;
    ((__nv_bfloat162*)lo)[1] = d;
}

__global__ __launch_bounds__(256) void transposeAll(
    const float* __restrict__ W0, const float* __restrict__ W1,
    const float* __restrict__ W2, const float* __restrict__ W3)
{
    __shared__ float t[32][33];
    const int w = blockIdx.z;
    const float* W = (w == 0) ? W0 : (w == 1) ? W1 : (w == 2) ? W2 : W3;
    bf16* Th = &g_Wth[0][0] + (size_t)w * NW;
    bf16* Tl = &g_Wtl[0][0] + (size_t)w * NW;
    int n0 = blockIdx.x << 5, k0 = blockIdx.y << 5;
    int tx = threadIdx.x, ty = threadIdx.y;
    for (int r = ty; r < 32; r += 8)
        t[r][tx] = W[(size_t)(k0 + r) * 1024 + n0 + tx];
    __syncthreads();
    for (int r = ty; r < 32; r += 8) {
        float v = t[tx][r];
        bf16 hh = __float2bfloat16(v);
        bf16 ll = __float2bfloat16(v - __bfloat162float(hh));
        Th[(size_t)(n0 + r) * 1024 + k0 + tx] = hh;
        Tl[(size_t)(n0 + r) * 1024 + k0 + tx] = ll;
    }
}

// ============================================================
// Launch
// ============================================================
extern "C" void kernel_launch(void* const* d_in, const int* in_sizes, int n_in,
                              void* d_out, int out_size)
{
    const float* x  = (const float*)d_in[0];
    const float* Wq = (const float*)d_in[1];
    const float* bq = (const float*)d_in[2];
    const float* Wk = (const float*)d_in[3];
    const float* bk = (const float*)d_in[4];
    const float* Wv = (const float*)d_in[5];
    const float* bv = (const float*)d_in[6];
    const float* Wo = (const float*)d_in[7];
    const float* bo = (const float*)d_in[8];
    float* out = (float*)d_out;

    static bool attr_set = false;
    if (!attr_set) {
        cudaFuncSetAttribute(hproj, cudaFuncAttributeMaxDynamicSharedMemorySize, GEMM_SMEM);
        cudaFuncSetAttribute(hout, cudaFuncAttributeMaxDynamicSharedMemorySize, GEMM_SMEM);
        cudaFuncSetAttribute(hattn, cudaFuncAttributeMaxDynamicSharedMemorySize, ATTN_SMEM);
        attr_set = true;
    }

    bf16 *Ah, *Al, *AOh, *AOl;
    cudaGetSymbolAddress((void**)&Ah, g_Ah);   cudaGetSymbolAddress((void**)&Al, g_Al);
    cudaGetSymbolAddress((void**)&AOh, g_AOh); cudaGetSymbolAddress((void**)&AOl, g_AOl);

    // 0: merged input split; 1: weight transposes
    split_all<<<24576, 256>>>(x);
    transposeAll<<<dim3(32, 32, 4), dim3(32, 8)>>>(Wq, Wk, Wv, Wo);
    // 2: batched QKV projections
    hproj<<<dim3(24, 64, 3), 256, GEMM_SMEM>>>(Ah, Al, bq, bk, bv);
    // 3: fully fused dual attention (bf16 scores, fp16 PV)
    hattn<<<dim3(16, 128), 256, ATTN_SMEM>>>();
    // 4: batched output projection
    hout<<<dim3(8, 64, 3), 256, GEMM_SMEM>>>(AOh, AOl, bo, out);
}

// round 11
// speedup vs baseline: 5.9906x; 1.3360x over previous
#include <cuda_runtime.h>
#include <cuda_fp16.h>
#include <cstdint>

typedef unsigned int u32;
typedef __half f16;

#define NN 8388608ULL      // 8192*1024
#define NW 1048576ULL      // 1024*1024

// ---------------- global scratch (all fp16) ----------------
__device__ f16 g_Ah[3][NN], g_Al[3][NN];         // x split hi/lo
__device__ f16 g_Qh[3][NN], g_Ql[3][NN];         // q split
__device__ f16 g_Kh[3][NN];                      // k hi only (2-term scores)
__device__ f16 g_Vh[3][NN], g_Vl[3][NN];         // v split
__device__ f16 g_AOh[3][NN], g_AOl[3][NN];       // attention out split
__device__ f16 g_Wth[4][NW];                     // W^T hi only [q,k,v,o]

// ---------------- PTX helpers ----------------
__device__ __forceinline__ u32 smem_u32(const void* p) {
    u32 a;
    asm("{ .reg .u64 t; cvta.to.shared.u64 t, %1; cvt.u32.u64 %0, t; }" : "=r"(a) : "l"(p));
    return a;
}
__device__ __forceinline__ void cp16(u32 d, const void* s) {
    asm volatile("cp.async.cg.shared.global [%0], [%1], 16;" :: "r"(d), "l"(s));
}
__device__ __forceinline__ void cpcommit() { asm volatile("cp.async.commit_group;"); }
template<int N> __device__ __forceinline__ void cpwait() {
    asm volatile("cp.async.wait_group %0;" :: "n"(N));
}
__device__ __forceinline__ void ldm4(u32* r, u32 a) {
    asm volatile("ldmatrix.sync.aligned.m8n8.x4.shared.b16 {%0,%1,%2,%3}, [%4];"
                 : "=r"(r[0]), "=r"(r[1]), "=r"(r[2]), "=r"(r[3]) : "r"(a));
}
__device__ __forceinline__ void ldm4t(u32* r, u32 a) {
    asm volatile("ldmatrix.sync.aligned.m8n8.x4.trans.shared.b16 {%0,%1,%2,%3}, [%4];"
                 : "=r"(r[0]), "=r"(r[1]), "=r"(r[2]), "=r"(r[3]) : "r"(a));
}
__device__ __forceinline__ void mma_fp(float* c, const u32* a, u32 b0, u32 b1) {
    asm volatile(
        "mma.sync.aligned.m16n8k16.row.col.f32.f16.f16.f32 "
        "{%0,%1,%2,%3}, {%4,%5,%6,%7}, {%8,%9}, {%0,%1,%2,%3};"
        : "+f"(c[0]), "+f"(c[1]), "+f"(c[2]), "+f"(c[3])
        : "r"(a[0]), "r"(a[1]), "r"(a[2]), "r"(a[3]), "r"(b0), "r"(b1));
}
__device__ __forceinline__ void wsplit2h(f16* H, f16* L, size_t off, float v0, float v1) {
    f16 h0 = __float2half_rn(v0); f16 l0 = __float2half_rn(v0 - __half2float(h0));
    f16 h1 = __float2half_rn(v1); f16 l1 = __float2half_rn(v1 - __half2float(h1));
    __half2 hh; hh.x = h0; hh.y = h1;
    __half2 ll; ll.x = l0; ll.y = l1;
    *(__half2*)(H + off) = hh;
    *(__half2*)(L + off) = ll;
}
__device__ __forceinline__ void wstore2h(f16* H, size_t off, float v0, float v1) {
    __half2 hh; hh.x = __float2half_rn(v0); hh.y = __float2half_rn(v1);
    *(__half2*)(H + off) = hh;
}
__device__ __forceinline__ void sts32(u32 a, u32 v) {
    asm volatile("st.shared.b32 [%0], %1;" :: "r"(a), "r"(v) : "memory");
}

// ============================================================
// GEMM core (fp16 2-term): 128x128 tile, BK=32, 256 thr, 8 warps
// (2m x 4n), warp 64x32. C = (Ah+Al) @ Bh^T. Double-buffered.
// smem: 3 matrices x 10240B per buffer.
// ============================================================
#define GMAT 10240
#define GBUF 30720
#define GEMM_SMEM 61440

__device__ __forceinline__ void stage_g(u32 sm,
    const f16* __restrict__ Ah, const f16* __restrict__ Al, int lda,
    const f16* __restrict__ Bh, int ldb, int k0, int tid)
{
    const int r = tid >> 2, cc = tid & 3;
    const u32 so = r * 80 + cc * 16;
    const int co = k0 + cc * 8;
    cp16(sm + so,                 Ah + (size_t)r * lda + co);
    cp16(sm + so + 5120,          Ah + (size_t)(r + 64) * lda + co);
    cp16(sm + GMAT + so,          Al + (size_t)r * lda + co);
    cp16(sm + GMAT + so + 5120,   Al + (size_t)(r + 64) * lda + co);
    cp16(sm + 2*GMAT + so,        Bh + (size_t)r * ldb + co);
    cp16(sm + 2*GMAT + so + 5120, Bh + (size_t)(r + 64) * ldb + co);
}

__device__ __forceinline__ void gemm_core(u32 sm,
    const f16* __restrict__ Ah, const f16* __restrict__ Al, int lda,
    const f16* __restrict__ Bh, int ldb, int nk, float c[4][4][4])
{
    const int tid = threadIdx.x, wid = tid >> 5, lane = tid & 31;
    const int wm = wid >> 2, wn = wid & 3;
    const int lr = lane & 15, lc = lane >> 4;

    stage_g(sm, Ah, Al, lda, Bh, ldb, 0, tid);
    cpcommit();

#pragma unroll 1
    for (int kt = 0; kt < nk; kt++) {
        if (kt + 1 < nk) {
            stage_g(sm + ((kt + 1) & 1) * GBUF, Ah, Al, lda, Bh, ldb, (kt + 1) * 32, tid);
            cpcommit();
            cpwait<1>();
        } else {
            cpwait<0>();
        }
        __syncthreads();
        const u32 base = sm + (kt & 1) * GBUF;
#pragma unroll
        for (int ks = 0; ks < 2; ks++) {
            u32 ah[4][4], al[4][4], bh[2][4];
            const u32 aoff = base + (wm * 64 + lr) * 80 + ks * 32 + lc * 16;
#pragma unroll
            for (int mf = 0; mf < 4; mf++) {
                ldm4(ah[mf], aoff + mf * 1280);
                ldm4(al[mf], aoff + mf * 1280 + GMAT);
            }
            const u32 boff = base + 2 * GMAT + (wn * 32 + lr) * 80 + ks * 32 + lc * 16;
#pragma unroll
            for (int g = 0; g < 2; g++)
                ldm4(bh[g], boff + g * 1280);
#pragma unroll
            for (int mf = 0; mf < 4; mf++)
#pragma unroll
                for (int nf = 0; nf < 4; nf++) {
                    const int g = nf >> 1, od = nf & 1;
                    mma_fp(c[mf][nf], ah[mf], bh[g][od], bh[g][od + 2]);
                    mma_fp(c[mf][nf], al[mf], bh[g][od], bh[g][od + 2]);
                }
        }
        __syncthreads();
    }
}

// ============================================================
// hproj: batched QKV projections. q -> split, k -> hi only, v -> split.
// ============================================================
__global__ __launch_bounds__(256, 2) void hproj(
    const f16* __restrict__ AhB, const f16* __restrict__ AlB,
    const float* __restrict__ bq, const float* __restrict__ bk,
    const float* __restrict__ bv)
{
    extern __shared__ __align__(16) char smraw[];
    const u32 sm = smem_u32(smraw);
    const int s = blockIdx.z;
    const int bm = blockIdx.y << 7;
    const int bnG = blockIdx.x << 7;
    const int p = bnG >> 10, bnL = bnG & 1023;

    const float* bias = (p == 0) ? bq : (p == 1) ? bk : bv;

    float c[4][4][4];
#pragma unroll
    for (int i = 0; i < 4; i++)
#pragma unroll
        for (int j = 0; j < 4; j++)
#pragma unroll
            for (int k = 0; k < 4; k++) c[i][j][k] = 0.f;

    gemm_core(sm, AhB + s * NN + (size_t)bm * 1024, AlB + s * NN + (size_t)bm * 1024, 1024,
              &g_Wth[0][0] + (size_t)bnG * 1024, 1024, 32, c);

    const int wid = threadIdx.x >> 5, lane = threadIdx.x & 31;
    const int wm = wid >> 2, wn = wid & 3;
    const int rbase = bm + wm * 64 + (lane >> 2);
    const int cbase = bnL + wn * 32 + 2 * (lane & 3);

    if (p == 1) {
        f16* oh = g_Kh[s];
#pragma unroll
        for (int mf = 0; mf < 4; mf++)
#pragma unroll
            for (int nf = 0; nf < 4; nf++) {
                const int col = cbase + nf * 8;
                const float b0 = bias[col], b1 = bias[col + 1];
                const int row = rbase + mf * 16;
                wstore2h(oh, (size_t)row * 1024 + col, c[mf][nf][0] + b0, c[mf][nf][1] + b1);
                wstore2h(oh, (size_t)(row + 8) * 1024 + col, c[mf][nf][2] + b0, c[mf][nf][3] + b1);
            }
    } else {
        f16* oh = (p == 0) ? g_Qh[s] : g_Vh[s];
        f16* ol = (p == 0) ? g_Ql[s] : g_Vl[s];
#pragma unroll
        for (int mf = 0; mf < 4; mf++)
#pragma unroll
            for (int nf = 0; nf < 4; nf++) {
                const int col = cbase + nf * 8;
                const float b0 = bias[col], b1 = bias[col + 1];
                const int row = rbase + mf * 16;
                wsplit2h(oh, ol, (size_t)row * 1024 + col, c[mf][nf][0] + b0, c[mf][nf][1] + b1);
                wsplit2h(oh, ol, (size_t)(row + 8) * 1024 + col, c[mf][nf][2] + b0, c[mf][nf][3] + b1);
            }
    }
}

// ============================================================
// hout: batched output projection
// ============================================================
__global__ __launch_bounds__(256, 2) void hout(
    const f16* __restrict__ AOhB, const f16* __restrict__ AOlB,
    const float* __restrict__ bo, float* __restrict__ out)
{
    extern __shared__ __align__(16) char smraw[];
    const u32 sm = smem_u32(smraw);
    const int s = blockIdx.z;
    const int bm = blockIdx.y << 7, bn = blockIdx.x << 7;

    float c[4][4][4];
#pragma unroll
    for (int i = 0; i < 4; i++)
#pragma unroll
        for (int j = 0; j < 4; j++)
#pragma unroll
            for (int k = 0; k < 4; k++) c[i][j][k] = 0.f;

    gemm_core(sm, AOhB + s * NN + (size_t)bm * 1024, AOlB + s * NN + (size_t)bm * 1024, 1024,
              &g_Wth[3][0] + (size_t)bn * 1024, 1024, 32, c);

    float* outF = out + s * 1024;
    const int wid = threadIdx.x >> 5, lane = threadIdx.x & 31;
    const int wm = wid >> 2, wn = wid & 3;
    const int rbase = bm + wm * 64 + (lane >> 2);
    const int cbase = bn + wn * 32 + 2 * (lane & 3);
#pragma unroll
    for (int mf = 0; mf < 4; mf++)
#pragma unroll
        for (int nf = 0; nf < 4; nf++) {
            const int col = cbase + nf * 8;
            const float b0 = bo[col], b1 = bo[col + 1];
            const int row = rbase + mf * 16;
            *(float2*)(outF + (size_t)row * 3072 + col) =
                make_float2(c[mf][nf][0] + b0, c[mf][nf][1] + b1);
            *(float2*)(outF + (size_t)(row + 8) * 3072 + col) =
                make_float2(c[mf][nf][2] + b0, c[mf][nf][3] + b1);
        }
}

// ============================================================
// hattn: fused dual attention, all 3 output streams per CTA.
// Scores: fp16 2-term (Qh+Ql)@Kh. P: fp16. PV: fp16 2-term P@(Vh+Vl).
// smem tiles (9216B each): Q 6, K 3, V 6, P 3 -> ~163KB + rowsums.
// ============================================================
#define AROW 144
#define ATILE 9216
#define AQ 0
#define AK 55296          // 3 tiles (K hi only)
#define AV 82944          // 6 tiles
#define AP 138240         // 3 tiles
#define ASL 165888
#define ATTN_SMEM 166656

__device__ __forceinline__ void stage64(u32 dst, const void* __restrict__ src16) {
    const char* src = (const char*)src16;
    const int t = threadIdx.x;
    const int r0 = t >> 3, cc = t & 7, r1 = r0 + 32;
    cp16(dst + r0 * AROW + cc * 16, src + (size_t)r0 * 2048 + cc * 16);
    cp16(dst + r1 * AROW + cc * 16, src + (size_t)r1 * 2048 + cc * 16);
}

__global__ __launch_bounds__(256, 1) void hattn()
{
    extern __shared__ __align__(16) char smraw[];
    const u32 sm = smem_u32(smraw);
    float* sL = (float*)(smraw + ASL);

    const int tid = threadIdx.x, wid = tid >> 5, lane = tid & 31;
    const int bh = blockIdx.y, b = bh >> 4, h = bh & 15;
    const int i0 = blockIdx.x << 6;

    const int wm = wid & 1, wn = wid >> 1;       // 2m x 4n
    const int lr = lane & 15, lc = lane >> 4;

    if (tid < 192) sL[tid] = 0.f;

    const size_t qoff = ((size_t)((b << 10) + i0)) * 1024 + (h << 6);
    const size_t koff = ((size_t)(b << 10)) * 1024 + (h << 6);
    const void* Qp[6] = { g_Qh[0] + qoff, g_Ql[0] + qoff, g_Qh[1] + qoff,
                          g_Ql[1] + qoff, g_Qh[2] + qoff, g_Ql[2] + qoff };
    const void* Kp[3] = { g_Kh[0] + koff, g_Kh[1] + koff, g_Kh[2] + koff };
    const void* Vp[6] = { g_Vh[0] + koff, g_Vl[0] + koff, g_Vh[1] + koff,
                          g_Vl[1] + koff, g_Vh[2] + koff, g_Vl[2] + koff };

    // prologue: group0 = {Q, K(0)}, group1 = {V(0)}
#pragma unroll
    for (int m = 0; m < 6; m++) stage64(sm + AQ + m * ATILE, Qp[m]);
#pragma unroll
    for (int m = 0; m < 3; m++) stage64(sm + AK + m * ATILE, Kp[m]);
    cpcommit();
#pragma unroll
    for (int m = 0; m < 6; m++) stage64(sm + AV + m * ATILE, Vp[m]);
    cpcommit();

    float co[3][2][2][4];
    float Lsum[3][4];
#pragma unroll
    for (int o = 0; o < 3; o++) {
#pragma unroll
        for (int i = 0; i < 4; i++) Lsum[o][i] = 0.f;
#pragma unroll
        for (int mf = 0; mf < 2; mf++)
#pragma unroll
            for (int nf = 0; nf < 2; nf++)
#pragma unroll
                for (int k = 0; k < 4; k++) co[o][mf][nf][k] = 0.f;
    }

#pragma unroll 1
    for (int kt = 0; kt < 16; kt++) {
        cpwait<1>();                 // Q + K(kt) ready
        __syncthreads();

        // ---- score MMAs: s_s = (Qh+Ql)_s @ Kh_s^T (fp16 2-term) ----
        float sc[3][2][2][4];
#pragma unroll
        for (int s3 = 0; s3 < 3; s3++)
#pragma unroll
            for (int mf = 0; mf < 2; mf++)
#pragma unroll
                for (int nf = 0; nf < 2; nf++)
#pragma unroll
                    for (int k = 0; k < 4; k++) sc[s3][mf][nf][k] = 0.f;

#pragma unroll
        for (int s3 = 0; s3 < 3; s3++) {
            const u32 qb = sm + AQ + (s3 * 2) * ATILE + (wm * 32 + lr) * AROW + lc * 16;
            const u32 kb = sm + AK + s3 * ATILE + (wn * 16 + lr) * AROW + lc * 16;
#pragma unroll
            for (int ks = 0; ks < 4; ks++) {
                u32 qh[2][4], ql[2][4], kh[4];
#pragma unroll
                for (int mf = 0; mf < 2; mf++) {
                    ldm4(qh[mf], qb + mf * 2304 + ks * 32);
                    ldm4(ql[mf], qb + mf * 2304 + ks * 32 + ATILE);
                }
                ldm4(kh, kb + ks * 32);
#pragma unroll
                for (int mf = 0; mf < 2; mf++)
#pragma unroll
                    for (int nf = 0; nf < 2; nf++) {
                        mma_fp(sc[s3][mf][nf], qh[mf], kh[nf], kh[nf + 2]);
                        mma_fp(sc[s3][mf][nf], ql[mf], kh[nf], kh[nf + 2]);
                    }
            }
        }
        __syncthreads();             // done reading K(kt)
        if (kt + 1 < 16) {
#pragma unroll
            for (int m = 0; m < 3; m++)
                stage64(sm + AK + m * ATILE, (const char*)Kp[m] + (size_t)(kt + 1) * 131072);
        }
        cpcommit();                  // group {K(kt+1)}

        // ---- p = exp((s_a + s_b)/16) -> fp16, to P smem ----
#pragma unroll
        for (int o = 0; o < 3; o++) {
            const int sa = (o == 0) ? 1 : 0;
            const int sb = (o == 2) ? 1 : 2;
#pragma unroll
            for (int mf = 0; mf < 2; mf++)
#pragma unroll
                for (int nf = 0; nf < 2; nf++) {
                    const float p0 = __expf((sc[sa][mf][nf][0] + sc[sb][mf][nf][0]) * 0.0625f);
                    const float p1 = __expf((sc[sa][mf][nf][1] + sc[sb][mf][nf][1]) * 0.0625f);
                    const float p2 = __expf((sc[sa][mf][nf][2] + sc[sb][mf][nf][2]) * 0.0625f);
                    const float p3 = __expf((sc[sa][mf][nf][3] + sc[sb][mf][nf][3]) * 0.0625f);
                    Lsum[o][mf * 2 + 0] += p0 + p1;
                    Lsum[o][mf * 2 + 1] += p2 + p3;
                    const int row = wm * 32 + mf * 16 + (lane >> 2);
                    const int col = wn * 16 + nf * 8 + 2 * (lane & 3);
                    const u32 ad = sm + AP + o * ATILE + row * AROW + col * 2;
                    __half2 t01; t01.x = __float2half_rn(p0); t01.y = __float2half_rn(p1);
                    __half2 t23; t23.x = __float2half_rn(p2); t23.y = __float2half_rn(p3);
                    sts32(ad,            *(u32*)&t01);
                    sts32(ad + 8 * AROW, *(u32*)&t23);
                }
        }

        cpwait<1>();                 // V(kt) ready
        __syncthreads();             // P visible

        // ---- PV MMAs (fp16): O_o += P_o @ (V_hi + V_lo) ----
#pragma unroll
        for (int o = 0; o < 3; o++) {
            const u32 pb = sm + AP + o * ATILE + (wm * 32 + lr) * AROW + lc * 16;
            const u32 vb = sm + AV + (o * 2) * ATILE + lr * AROW + wn * 32 + lc * 16;
#pragma unroll
            for (int ks = 0; ks < 4; ks++) {
                u32 ph[2][4], vh[4], vl[4];
#pragma unroll
                for (int mf = 0; mf < 2; mf++)
                    ldm4(ph[mf], pb + mf * 2304 + ks * 32);
                ldm4t(vh, vb + ks * 16 * AROW);
                ldm4t(vl, vb + ks * 16 * AROW + ATILE);
#pragma unroll
                for (int mf = 0; mf < 2; mf++)
#pragma unroll
                    for (int nf = 0; nf < 2; nf++) {
                        mma_fp(co[o][mf][nf], ph[mf], vh[2 * nf], vh[2 * nf + 1]);
                        mma_fp(co[o][mf][nf], ph[mf], vl[2 * nf], vl[2 * nf + 1]);
                    }
            }
        }
        __syncthreads();             // done reading V(kt) and P
        if (kt + 1 < 16) {
#pragma unroll
            for (int m = 0; m < 6; m++)
                stage64(sm + AV + m * ATILE, (const char*)Vp[m] + (size_t)(kt + 1) * 131072);
        }
        cpcommit();                  // group {V(kt+1)}
    }

    // ---- row-sum reduction into sL ----
#pragma unroll
    for (int o = 0; o < 3; o++)
#pragma unroll
        for (int sl = 0; sl < 4; sl++) {
            float v = Lsum[o][sl];
            v += __shfl_xor_sync(0xffffffffu, v, 1);
            v += __shfl_xor_sync(0xffffffffu, v, 2);
            if ((lane & 3) == 0) {
                const int row = wm * 32 + (sl >> 1) * 16 + (lane >> 2) + (sl & 1) * 8;
                atomicAdd(&sL[o * 64 + row], v);
            }
        }
    __syncthreads();

    // ---- epilogue: normalize + write AO split (fp16) ----
#pragma unroll
    for (int o = 0; o < 3; o++) {
        f16* AH = g_AOh[o];
        f16* AL = g_AOl[o];
#pragma unroll
        for (int mf = 0; mf < 2; mf++)
#pragma unroll
            for (int nf = 0; nf < 2; nf++) {
                const int rl0 = wm * 32 + mf * 16 + (lane >> 2);
                const int rl1 = rl0 + 8;
                const int cl = wn * 16 + nf * 8 + 2 * (lane & 3);
                const float iv0 = 1.0f / sL[o * 64 + rl0];
                const float iv1 = 1.0f / sL[o * 64 + rl1];
                const size_t ga = ((size_t)((b << 10) + i0 + rl0)) * 1024 + (h << 6) + cl;
                const size_t gb2 = ((size_t)((b << 10) + i0 + rl1)) * 1024 + (h << 6) + cl;
                wsplit2h(AH, AL, ga,  co[o][mf][nf][0] * iv0, co[o][mf][nf][1] * iv0);
                wsplit2h(AH, AL, gb2, co[o][mf][nf][2] * iv1, co[o][mf][nf][3] * iv1);
            }
    }
}

// ============================================================
// split_all: all 3 stream splits (fp16 hi/lo) in one launch
// ============================================================
__global__ __launch_bounds__(256) void split_all(const float* __restrict__ x)
{
    const size_t gid = (size_t)blockIdx.x * 256 + threadIdx.x;
    const int s = (int)(gid >> 21);
    const size_t t = gid & 2097151ULL;
    const size_t idx = t * 4;
    const int m = (int)(idx >> 10), col = (int)(idx & 1023);
    const float4 v = *(const float4*)(x + ((size_t)m * 3 + s) * 1024 + col);
    f16* hi = &g_Ah[0][0] + s * NN + idx;
    f16* lo = &g_Al[0][0] + s * NN + idx;
    f16 h0 = __float2half_rn(v.x); f16 l0 = __float2half_rn(v.x - __half2float(h0));
    f16 h1 = __float2half_rn(v.y); f16 l1 = __float2half_rn(v.y - __half2float(h1));
    f16 h2 = __float2half_rn(v.z); f16 l2 = __float2half_rn(v.z - __half2float(h2));
    f16 h3 = __float2half_rn(v.w); f16 l3 = __float2half_rn(v.w - __half2float(h3));
    __half2 a; a.x = h0; a.y = h1;
    __half2 bb; bb.x = h2; bb.y = h3;
    __half2 cc; cc.x = l0; cc.y = l1;
    __half2 d; d.x = l2; d.y = l3;
    ((__half2*)hi)[0] = a;
    ((__half2*)hi)[1] = bb;
    ((__half2*)lo)[0] = cc;
    ((__half2*)lo)[1] = d;
}

// ============================================================
// transposeAll: W^T hi (fp16) for all 4 weights
// ============================================================
__global__ __launch_bounds__(256) void transposeAll(
    const float* __restrict__ W0, const float* __restrict__ W1,
    const float* __restrict__ W2, const float* __restrict__ W3)
{
    __shared__ float t[32][33];
    const int w = blockIdx.z;
    const float* W = (w == 0) ? W0 : (w == 1) ? W1 : (w == 2) ? W2 : W3;
    f16* Th = &g_Wth[0][0] + (size_t)w * NW;
    int n0 = blockIdx.x << 5, k0 = blockIdx.y << 5;
    int tx = threadIdx.x, ty = threadIdx.y;
    for (int r = ty; r < 32; r += 8)
        t[r][tx] = W[(size_t)(k0 + r) * 1024 + n0 + tx];
    __syncthreads();
    for (int r = ty; r < 32; r += 8)
        Th[(size_t)(n0 + r) * 1024 + k0 + tx] = __float2half_rn(t[tx][r]);
}

// ============================================================
// Launch
// ============================================================
extern "C" void kernel_launch(void* const* d_in, const int* in_sizes, int n_in,
                              void* d_out, int out_size)
{
    const float* x  = (const float*)d_in[0];
    const float* Wq = (const float*)d_in[1];
    const float* bq = (const float*)d_in[2];
    const float* Wk = (const float*)d_in[3];
    const float* bk = (const float*)d_in[4];
    const float* Wv = (const float*)d_in[5];
    const float* bv = (const float*)d_in[6];
    const float* Wo = (const float*)d_in[7];
    const float* bo = (const float*)d_in[8];
    float* out = (float*)d_out;

    static bool attr_set = false;
    if (!attr_set) {
        cudaFuncSetAttribute(hproj, cudaFuncAttributeMaxDynamicSharedMemorySize, GEMM_SMEM);
        cudaFuncSetAttribute(hout, cudaFuncAttributeMaxDynamicSharedMemorySize, GEMM_SMEM);
        cudaFuncSetAttribute(hattn, cudaFuncAttributeMaxDynamicSharedMemorySize, ATTN_SMEM);
        attr_set = true;
    }

    f16 *Ah, *Al, *AOh, *AOl;
    cudaGetSymbolAddress((void**)&Ah, g_Ah);   cudaGetSymbolAddress((void**)&Al, g_Al);
    cudaGetSymbolAddress((void**)&AOh, g_AOh); cudaGetSymbolAddress((void**)&AOl, g_AOl);

    split_all<<<24576, 256>>>(x);
    transposeAll<<<dim3(32, 32, 4), dim3(32, 8)>>>(Wq, Wk, Wv, Wo);
    hproj<<<dim3(24, 64, 3), 256, GEMM_SMEM>>>(Ah, Al, bq, bk, bv);
    hattn<<<dim3(16, 128), 256, ATTN_SMEM>>>();
    hout<<<dim3(8, 64, 3), 256, GEMM_SMEM>>>(AOh, AOl, bo, out);
}

// round 12
// speedup vs baseline: 9.8161x; 1.6386x over previous
#include <cuda_runtime.h>
#include <cuda_fp16.h>
#include <cstdint>

typedef unsigned int u32;
typedef __half f16;

#define NN 8388608ULL      // 8192*1024
#define NW 1048576ULL      // 1024*1024

// ---------------- global scratch (single fp16 everywhere) ----------------
__device__ f16 g_Ah[3][NN];          // x fp16
__device__ f16 g_Qh[3][NN];          // q
__device__ f16 g_Kh[3][NN];          // k
__device__ f16 g_Vh[3][NN];          // v
__device__ f16 g_AOh[3][NN];         // attention out
__device__ f16 g_Wth[4][NW];         // W^T [q,k,v,o]

// ---------------- PTX helpers ----------------
__device__ __forceinline__ u32 smem_u32(const void* p) {
    u32 a;
    asm("{ .reg .u64 t; cvta.to.shared.u64 t, %1; cvt.u32.u64 %0, t; }" : "=r"(a) : "l"(p));
    return a;
}
__device__ __forceinline__ void cp16(u32 d, const void* s) {
    asm volatile("cp.async.cg.shared.global [%0], [%1], 16;" :: "r"(d), "l"(s));
}
__device__ __forceinline__ void cpcommit() { asm volatile("cp.async.commit_group;"); }
template<int N> __device__ __forceinline__ void cpwait() {
    asm volatile("cp.async.wait_group %0;" :: "n"(N));
}
__device__ __forceinline__ void ldm4(u32* r, u32 a) {
    asm volatile("ldmatrix.sync.aligned.m8n8.x4.shared.b16 {%0,%1,%2,%3}, [%4];"
                 : "=r"(r[0]), "=r"(r[1]), "=r"(r[2]), "=r"(r[3]) : "r"(a));
}
__device__ __forceinline__ void ldm4t(u32* r, u32 a) {
    asm volatile("ldmatrix.sync.aligned.m8n8.x4.trans.shared.b16 {%0,%1,%2,%3}, [%4];"
                 : "=r"(r[0]), "=r"(r[1]), "=r"(r[2]), "=r"(r[3]) : "r"(a));
}
__device__ __forceinline__ void mma_fp(float* c, const u32* a, u32 b0, u32 b1) {
    asm volatile(
        "mma.sync.aligned.m16n8k16.row.col.f32.f16.f16.f32 "
        "{%0,%1,%2,%3}, {%4,%5,%6,%7}, {%8,%9}, {%0,%1,%2,%3};"
        : "+f"(c[0]), "+f"(c[1]), "+f"(c[2]), "+f"(c[3])
        : "r"(a[0]), "r"(a[1]), "r"(a[2]), "r"(a[3]), "r"(b0), "r"(b1));
}
__device__ __forceinline__ void wstore2h(f16* H, size_t off, float v0, float v1) {
    __half2 hh; hh.x = __float2half_rn(v0); hh.y = __float2half_rn(v1);
    *(__half2*)(H + off) = hh;
}
__device__ __forceinline__ void sts32(u32 a, u32 v) {
    asm volatile("st.shared.b32 [%0], %1;" :: "r"(a), "r"(v) : "memory");
}

// ============================================================
// GEMM core (fp16 single-term): 128x128 tile, BK=32, 256 thr,
// 8 warps (2m x 4n), warp 64x32. C = A @ B^T. Double-buffered.
// smem: 2 matrices x 10240B per buffer.
// ============================================================
#define GMAT 10240
#define GBUF 20480
#define GEMM_SMEM 40960

__device__ __forceinline__ void stage_g(u32 sm,
    const f16* __restrict__ A, int lda,
    const f16* __restrict__ B, int ldb, int k0, int tid)
{
    const int r = tid >> 2, cc = tid & 3;
    const u32 so = r * 80 + cc * 16;
    const int co = k0 + cc * 8;
    cp16(sm + so,               A + (size_t)r * lda + co);
    cp16(sm + so + 5120,        A + (size_t)(r + 64) * lda + co);
    cp16(sm + GMAT + so,        B + (size_t)r * ldb + co);
    cp16(sm + GMAT + so + 5120, B + (size_t)(r + 64) * ldb + co);
}

__device__ __forceinline__ void gemm_core(u32 sm,
    const f16* __restrict__ A, int lda,
    const f16* __restrict__ B, int ldb, int nk, float c[4][4][4])
{
    const int tid = threadIdx.x, wid = tid >> 5, lane = tid & 31;
    const int wm = wid >> 2, wn = wid & 3;
    const int lr = lane & 15, lc = lane >> 4;

    stage_g(sm, A, lda, B, ldb, 0, tid);
    cpcommit();

#pragma unroll 1
    for (int kt = 0; kt < nk; kt++) {
        if (kt + 1 < nk) {
            stage_g(sm + ((kt + 1) & 1) * GBUF, A, lda, B, ldb, (kt + 1) * 32, tid);
            cpcommit();
            cpwait<1>();
        } else {
            cpwait<0>();
        }
        __syncthreads();
        const u32 base = sm + (kt & 1) * GBUF;
#pragma unroll
        for (int ks = 0; ks < 2; ks++) {
            u32 ah[4][4], bh[2][4];
            const u32 aoff = base + (wm * 64 + lr) * 80 + ks * 32 + lc * 16;
#pragma unroll
            for (int mf = 0; mf < 4; mf++)
                ldm4(ah[mf], aoff + mf * 1280);
            const u32 boff = base + GMAT + (wn * 32 + lr) * 80 + ks * 32 + lc * 16;
#pragma unroll
            for (int g = 0; g < 2; g++)
                ldm4(bh[g], boff + g * 1280);
#pragma unroll
            for (int mf = 0; mf < 4; mf++)
#pragma unroll
                for (int nf = 0; nf < 4; nf++) {
                    const int g = nf >> 1, od = nf & 1;
                    mma_fp(c[mf][nf], ah[mf], bh[g][od], bh[g][od + 2]);
                }
        }
        __syncthreads();
    }
}

// ============================================================
// hproj: batched QKV projections -> fp16 q/k/v
// ============================================================
__global__ __launch_bounds__(256, 2) void hproj(
    const f16* __restrict__ AB,
    const float* __restrict__ bq, const float* __restrict__ bk,
    const float* __restrict__ bv)
{
    extern __shared__ __align__(16) char smraw[];
    const u32 sm = smem_u32(smraw);
    const int s = blockIdx.z;
    const int bm = blockIdx.y << 7;
    const int bnG = blockIdx.x << 7;
    const int p = bnG >> 10, bnL = bnG & 1023;

    const float* bias = (p == 0) ? bq : (p == 1) ? bk : bv;
    f16* oh = (p == 0) ? g_Qh[s] : (p == 1) ? g_Kh[s] : g_Vh[s];

    float c[4][4][4];
#pragma unroll
    for (int i = 0; i < 4; i++)
#pragma unroll
        for (int j = 0; j < 4; j++)
#pragma unroll
            for (int k = 0; k < 4; k++) c[i][j][k] = 0.f;

    gemm_core(sm, AB + s * NN + (size_t)bm * 1024, 1024,
              &g_Wth[0][0] + (size_t)bnG * 1024, 1024, 32, c);

    const int wid = threadIdx.x >> 5, lane = threadIdx.x & 31;
    const int wm = wid >> 2, wn = wid & 3;
    const int rbase = bm + wm * 64 + (lane >> 2);
    const int cbase = bnL + wn * 32 + 2 * (lane & 3);
#pragma unroll
    for (int mf = 0; mf < 4; mf++)
#pragma unroll
        for (int nf = 0; nf < 4; nf++) {
            const int col = cbase + nf * 8;
            const float b0 = bias[col], b1 = bias[col + 1];
            const int row = rbase + mf * 16;
            wstore2h(oh, (size_t)row * 1024 + col, c[mf][nf][0] + b0, c[mf][nf][1] + b1);
            wstore2h(oh, (size_t)(row + 8) * 1024 + col, c[mf][nf][2] + b0, c[mf][nf][3] + b1);
        }
}

// ============================================================
// hout: batched output projection -> fp32 (B,L,3,D)
// ============================================================
__global__ __launch_bounds__(256, 2) void hout(
    const f16* __restrict__ AOB,
    const float* __restrict__ bo, float* __restrict__ out)
{
    extern __shared__ __align__(16) char smraw[];
    const u32 sm = smem_u32(smraw);
    const int s = blockIdx.z;
    const int bm = blockIdx.y << 7, bn = blockIdx.x << 7;

    float c[4][4][4];
#pragma unroll
    for (int i = 0; i < 4; i++)
#pragma unroll
        for (int j = 0; j < 4; j++)
#pragma unroll
            for (int k = 0; k < 4; k++) c[i][j][k] = 0.f;

    gemm_core(sm, AOB + s * NN + (size_t)bm * 1024, 1024,
              &g_Wth[3][0] + (size_t)bn * 1024, 1024, 32, c);

    float* outF = out + s * 1024;
    const int wid = threadIdx.x >> 5, lane = threadIdx.x & 31;
    const int wm = wid >> 2, wn = wid & 3;
    const int rbase = bm + wm * 64 + (lane >> 2);
    const int cbase = bn + wn * 32 + 2 * (lane & 3);
#pragma unroll
    for (int mf = 0; mf < 4; mf++)
#pragma unroll
        for (int nf = 0; nf < 4; nf++) {
            const int col = cbase + nf * 8;
            const float b0 = bo[col], b1 = bo[col + 1];
            const int row = rbase + mf * 16;
            *(float2*)(outF + (size_t)row * 3072 + col) =
                make_float2(c[mf][nf][0] + b0, c[mf][nf][1] + b1);
            *(float2*)(outF + (size_t)(row + 8) * 3072 + col) =
                make_float2(c[mf][nf][2] + b0, c[mf][nf][3] + b1);
        }
}

// ============================================================
// hattn: fused dual attention, all 3 output streams per CTA.
// All operands single fp16: s = Q@K^T, p = exp(s_a+s_b scaled) fp16,
// O = P@V normalized by rowsum. smem: Q3+K3+V3+P3 tiles = ~109KB.
// ============================================================
#define AROW 144
#define ATILE 9216
#define AQ 0
#define AK 27648
#define AV 55296
#define AP 82944
#define ASL 110592
#define ATTN_SMEM 111360

__device__ __forceinline__ void stage64(u32 dst, const void* __restrict__ src16) {
    const char* src = (const char*)src16;
    const int t = threadIdx.x;
    const int r0 = t >> 3, cc = t & 7, r1 = r0 + 32;
    cp16(dst + r0 * AROW + cc * 16, src + (size_t)r0 * 2048 + cc * 16);
    cp16(dst + r1 * AROW + cc * 16, src + (size_t)r1 * 2048 + cc * 16);
}

__global__ __launch_bounds__(256, 1) void hattn()
{
    extern __shared__ __align__(16) char smraw[];
    const u32 sm = smem_u32(smraw);
    float* sL = (float*)(smraw + ASL);

    const int tid = threadIdx.x, wid = tid >> 5, lane = tid & 31;
    const int bh = blockIdx.y, b = bh >> 4, h = bh & 15;
    const int i0 = blockIdx.x << 6;

    const int wm = wid & 1, wn = wid >> 1;       // 2m x 4n
    const int lr = lane & 15, lc = lane >> 4;

    if (tid < 192) sL[tid] = 0.f;

    const size_t qoff = ((size_t)((b << 10) + i0)) * 1024 + (h << 6);
    const size_t koff = ((size_t)(b << 10)) * 1024 + (h << 6);
    const void* Qp[3] = { g_Qh[0] + qoff, g_Qh[1] + qoff, g_Qh[2] + qoff };
    const void* Kp[3] = { g_Kh[0] + koff, g_Kh[1] + koff, g_Kh[2] + koff };
    const void* Vp[3] = { g_Vh[0] + koff, g_Vh[1] + koff, g_Vh[2] + koff };

    // prologue: group0 = {Q, K(0)}, group1 = {V(0)}
#pragma unroll
    for (int m = 0; m < 3; m++) stage64(sm + AQ + m * ATILE, Qp[m]);
#pragma unroll
    for (int m = 0; m < 3; m++) stage64(sm + AK + m * ATILE, Kp[m]);
    cpcommit();
#pragma unroll
    for (int m = 0; m < 3; m++) stage64(sm + AV + m * ATILE, Vp[m]);
    cpcommit();

    float co[3][2][2][4];
    float Lsum[3][4];
#pragma unroll
    for (int o = 0; o < 3; o++) {
#pragma unroll
        for (int i = 0; i < 4; i++) Lsum[o][i] = 0.f;
#pragma unroll
        for (int mf = 0; mf < 2; mf++)
#pragma unroll
            for (int nf = 0; nf < 2; nf++)
#pragma unroll
                for (int k = 0; k < 4; k++) co[o][mf][nf][k] = 0.f;
    }

#pragma unroll 1
    for (int kt = 0; kt < 16; kt++) {
        cpwait<1>();                 // Q + K(kt) ready
        __syncthreads();

        // ---- score MMAs: s_s = Q_s @ K_s^T ----
        float sc[3][2][2][4];
#pragma unroll
        for (int s3 = 0; s3 < 3; s3++)
#pragma unroll
            for (int mf = 0; mf < 2; mf++)
#pragma unroll
                for (int nf = 0; nf < 2; nf++)
#pragma unroll
                    for (int k = 0; k < 4; k++) sc[s3][mf][nf][k] = 0.f;

#pragma unroll
        for (int s3 = 0; s3 < 3; s3++) {
            const u32 qb = sm + AQ + s3 * ATILE + (wm * 32 + lr) * AROW + lc * 16;
            const u32 kb = sm + AK + s3 * ATILE + (wn * 16 + lr) * AROW + lc * 16;
#pragma unroll
            for (int ks = 0; ks < 4; ks++) {
                u32 qh[2][4], kh[4];
#pragma unroll
                for (int mf = 0; mf < 2; mf++)
                    ldm4(qh[mf], qb + mf * 2304 + ks * 32);
                ldm4(kh, kb + ks * 32);
#pragma unroll
                for (int mf = 0; mf < 2; mf++)
#pragma unroll
                    for (int nf = 0; nf < 2; nf++)
                        mma_fp(sc[s3][mf][nf], qh[mf], kh[nf], kh[nf + 2]);
            }
        }
        __syncthreads();             // done reading K(kt)
        if (kt + 1 < 16) {
#pragma unroll
            for (int m = 0; m < 3; m++)
                stage64(sm + AK + m * ATILE, (const char*)Kp[m] + (size_t)(kt + 1) * 131072);
        }
        cpcommit();                  // group {K(kt+1)}

        // ---- p = exp((s_a + s_b)/16) -> fp16, to P smem ----
#pragma unroll
        for (int o = 0; o < 3; o++) {
            const int sa = (o == 0) ? 1 : 0;
            const int sb = (o == 2) ? 1 : 2;
#pragma unroll
            for (int mf = 0; mf < 2; mf++)
#pragma unroll
                for (int nf = 0; nf < 2; nf++) {
                    const float p0 = __expf((sc[sa][mf][nf][0] + sc[sb][mf][nf][0]) * 0.0625f);
                    const float p1 = __expf((sc[sa][mf][nf][1] + sc[sb][mf][nf][1]) * 0.0625f);
                    const float p2 = __expf((sc[sa][mf][nf][2] + sc[sb][mf][nf][2]) * 0.0625f);
                    const float p3 = __expf((sc[sa][mf][nf][3] + sc[sb][mf][nf][3]) * 0.0625f);
                    Lsum[o][mf * 2 + 0] += p0 + p1;
                    Lsum[o][mf * 2 + 1] += p2 + p3;
                    const int row = wm * 32 + mf * 16 + (lane >> 2);
                    const int col = wn * 16 + nf * 8 + 2 * (lane & 3);
                    const u32 ad = sm + AP + o * ATILE + row * AROW + col * 2;
                    __half2 t01; t01.x = __float2half_rn(p0); t01.y = __float2half_rn(p1);
                    __half2 t23; t23.x = __float2half_rn(p2); t23.y = __float2half_rn(p3);
                    sts32(ad,            *(u32*)&t01);
                    sts32(ad + 8 * AROW, *(u32*)&t23);
                }
        }

        cpwait<1>();                 // V(kt) ready
        __syncthreads();             // P visible

        // ---- PV MMAs: O_o += P_o @ V_o ----
#pragma unroll
        for (int o = 0; o < 3; o++) {
            const u32 pb = sm + AP + o * ATILE + (wm * 32 + lr) * AROW + lc * 16;
            const u32 vb = sm + AV + o * ATILE + lr * AROW + wn * 32 + lc * 16;
#pragma unroll
            for (int ks = 0; ks < 4; ks++) {
                u32 ph[2][4], vh[4];
#pragma unroll
                for (int mf = 0; mf < 2; mf++)
                    ldm4(ph[mf], pb + mf * 2304 + ks * 32);
                ldm4t(vh, vb + ks * 16 * AROW);
#pragma unroll
                for (int mf = 0; mf < 2; mf++)
#pragma unroll
                    for (int nf = 0; nf < 2; nf++)
                        mma_fp(co[o][mf][nf], ph[mf], vh[2 * nf], vh[2 * nf + 1]);
            }
        }
        __syncthreads();             // done reading V(kt) and P
        if (kt + 1 < 16) {
#pragma unroll
            for (int m = 0; m < 3; m++)
                stage64(sm + AV + m * ATILE, (const char*)Vp[m] + (size_t)(kt + 1) * 131072);
        }
        cpcommit();                  // group {V(kt+1)}
    }

    // ---- row-sum reduction into sL ----
#pragma unroll
    for (int o = 0; o < 3; o++)
#pragma unroll
        for (int sl = 0; sl < 4; sl++) {
            float v = Lsum[o][sl];
            v += __shfl_xor_sync(0xffffffffu, v, 1);
            v += __shfl_xor_sync(0xffffffffu, v, 2);
            if ((lane & 3) == 0) {
                const int row = wm * 32 + (sl >> 1) * 16 + (lane >> 2) + (sl & 1) * 8;
                atomicAdd(&sL[o * 64 + row], v);
            }
        }
    __syncthreads();

    // ---- epilogue: normalize + write AO (fp16) ----
#pragma unroll
    for (int o = 0; o < 3; o++) {
        f16* AH = g_AOh[o];
#pragma unroll
        for (int mf = 0; mf < 2; mf++)
#pragma unroll
            for (int nf = 0; nf < 2; nf++) {
                const int rl0 = wm * 32 + mf * 16 + (lane >> 2);
                const int rl1 = rl0 + 8;
                const int cl = wn * 16 + nf * 8 + 2 * (lane & 3);
                const float iv0 = 1.0f / sL[o * 64 + rl0];
                const float iv1 = 1.0f / sL[o * 64 + rl1];
                const size_t ga = ((size_t)((b << 10) + i0 + rl0)) * 1024 + (h << 6) + cl;
                const size_t gb2 = ((size_t)((b << 10) + i0 + rl1)) * 1024 + (h << 6) + cl;
                wstore2h(AH, ga,  co[o][mf][nf][0] * iv0, co[o][mf][nf][1] * iv0);
                wstore2h(AH, gb2, co[o][mf][nf][2] * iv1, co[o][mf][nf][3] * iv1);
            }
    }
}

// ============================================================
// split_all: x -> fp16 (hi only), all 3 streams, one launch
// ============================================================
__global__ __launch_bounds__(256) void split_all(const float* __restrict__ x)
{
    const size_t gid = (size_t)blockIdx.x * 256 + threadIdx.x;
    const int s = (int)(gid >> 21);
    const size_t t = gid & 2097151ULL;
    const size_t idx = t * 4;
    const int m = (int)(idx >> 10), col = (int)(idx & 1023);
    const float4 v = *(const float4*)(x + ((size_t)m * 3 + s) * 1024 + col);
    f16* hi = &g_Ah[0][0] + s * NN + idx;
    __half2 a; a.x = __float2half_rn(v.x); a.y = __float2half_rn(v.y);
    __half2 bb; bb.x = __float2half_rn(v.z); bb.y = __float2half_rn(v.w);
    ((__half2*)hi)[0] = a;
    ((__half2*)hi)[1] = bb;
}

// ============================================================
// transposeAll: W^T (fp16) for all 4 weights
// ============================================================
__global__ __launch_bounds__(256) void transposeAll(
    const float* __restrict__ W0, const float* __restrict__ W1,
    const float* __restrict__ W2, const float* __restrict__ W3)
{
    __shared__ float t[32][33];
    const int w = blockIdx.z;
    const float* W = (w == 0) ? W0 : (w == 1) ? W1 : (w == 2) ? W2 : W3;
    f16* Th = &g_Wth[0][0] + (size_t)w * NW;
    int n0 = blockIdx.x << 5, k0 = blockIdx.y << 5;
    int tx = threadIdx.x, ty = threadIdx.y;
    for (int r = ty; r < 32; r += 8)
        t[r][tx] = W[(size_t)(k0 + r) * 1024 + n0 + tx];
    __syncthreads();
    for (int r = ty; r < 32; r += 8)
        Th[(size_t)(n0 + r) * 1024 + k0 + tx] = __float2half_rn(t[tx][r]);
}

// ============================================================
// Launch
// ============================================================
extern "C" void kernel_launch(void* const* d_in, const int* in_sizes, int n_in,
                              void* d_out, int out_size)
{
    const float* x  = (const float*)d_in[0];
    const float* Wq = (const float*)d_in[1];
    const float* bq = (const float*)d_in[2];
    const float* Wk = (const float*)d_in[3];
    const float* bk = (const float*)d_in[4];
    const float* Wv = (const float*)d_in[5];
    const float* bv = (const float*)d_in[6];
    const float* Wo = (const float*)d_in[7];
    const float* bo = (const float*)d_in[8];
    float* out = (float*)d_out;

    static bool attr_set = false;
    if (!attr_set) {
        cudaFuncSetAttribute(hproj, cudaFuncAttributeMaxDynamicSharedMemorySize, GEMM_SMEM);
        cudaFuncSetAttribute(hout, cudaFuncAttributeMaxDynamicSharedMemorySize, GEMM_SMEM);
        cudaFuncSetAttribute(hattn, cudaFuncAttributeMaxDynamicSharedMemorySize, ATTN_SMEM);
        attr_set = true;
    }

    f16 *Ah, *AOh;
    cudaGetSymbolAddress((void**)&Ah, g_Ah);
    cudaGetSymbolAddress((void**)&AOh, g_AOh);

    split_all<<<24576, 256>>>(x);
    transposeAll<<<dim3(32, 32, 4), dim3(32, 8)>>>(Wq, Wk, Wv, Wo);
    hproj<<<dim3(24, 64, 3), 256, GEMM_SMEM>>>(Ah, bq, bk, bv);
    hattn<<<dim3(16, 128), 256, ATTN_SMEM>>>();
    hout<<<dim3(8, 64, 3), 256, GEMM_SMEM>>>(AOh, bo, out);
}